// round 6
// baseline (speedup 1.0000x reference)
#include <cuda_runtime.h>
#include <math.h>
#include <stdint.h>

#define ENC 1024
#define PRED 320
#define JH 512
#define VOCAB 29
#define BLANK 28
#define MAXSYM 6
#define BATCH 32
#define TLEN 48
#define NSTEPS 288
#define ZDIM 1344
#define CSIZE 8                    // CTAs per cluster
#define MB 2                       // batch rows per cluster
#define NTHREADS 512
#define UNITS_PER (PRED / CSIZE)   // 40 LSTM units per CTA
#define GROWS_PER (4 * UNITS_PER)  // 160 gate rows per CTA
#define JROWS_PER (JH / CSIZE)     // 64 joint rows per CTA

#define CLUSTER_SYNC() do { \
    asm volatile("barrier.cluster.arrive.aligned;" ::: "memory"); \
    asm volatile("barrier.cluster.wait.aligned;"   ::: "memory"); \
} while (0)

__device__ __forceinline__ float sigf(float v) { return 1.0f / (1.0f + expf(-v)); }

__device__ __forceinline__ uint32_t s2u(const void* p) {
    return (uint32_t)__cvta_generic_to_shared((void*)p);
}

// store v into the SMEM copy of `addr` in cluster CTA `rank`
__device__ __forceinline__ void st_peer(uint32_t addr, int rank, float v) {
    uint32_t pa;
    asm volatile("mapa.shared::cluster.u32 %0, %1, %2;" : "=r"(pa) : "r"(addr), "r"(rank));
    asm volatile("st.shared::cluster.f32 [%0], %1;" :: "r"(pa), "f"(v));
}

// 4 interleaved butterfly-free shfl-down reductions (independent chains -> ILP)
__device__ __forceinline__ void redsum4(float& a, float& b, float& c, float& d) {
    #pragma unroll
    for (int o = 16; o > 0; o >>= 1) {
        a += __shfl_down_sync(0xffffffffu, a, o);
        b += __shfl_down_sync(0xffffffffu, b, o);
        c += __shfl_down_sync(0xffffffffu, c, o);
        d += __shfl_down_sync(0xffffffffu, d, o);
    }
}

// Gate GEMV: 160 local rows (4 gates x 40 units), width 640 = [A(320);B(320)], 2 batch rows.
// lanes 0-15 cover A cols [20*lane,+20); lanes 16-31 cover B cols [20*(lane-16),+20).
// Rows processed in pairs: 10 independent LDG.128 in flight, 4 interleaved reductions.
__device__ __forceinline__ void gemv_gates(
    const float* __restrict__ Wi, const float* __restrict__ Wh, const float* __restrict__ bias,
    const float* sA0, const float* sA1,
    const float* sB0, const float* sB1,
    float* g0, float* g1,
    int rank, int warp, int lane)
{
    const int  colbase = 20 * (lane & 15);
    const bool loA = (lane < 16);
    const float* a0 = (loA ? sA0 : sB0) + colbase;
    const float* a1 = (loA ? sA1 : sB1) + colbase;
    float4 v0[5], v1[5];
    #pragma unroll
    for (int j = 0; j < 5; ++j) {
        v0[j] = *(const float4*)(a0 + 4 * j);
        v1[j] = *(const float4*)(a1 + 4 * j);
    }
    const float* Wsel = loA ? Wi : Wh;
    #pragma unroll
    for (int pp = 0; pp < 5; ++pp) {                 // 10 rows/warp as 5 pairs
        int r0 = warp * 10 + 2 * pp;
        int r1 = r0 + 1;
        int ga = r0 / UNITS_PER, la = r0 - ga * UNITS_PER;
        int gb = r1 / UNITS_PER, lb = r1 - gb * UNITS_PER;
        int grow0 = ga * PRED + rank * UNITS_PER + la;
        int grow1 = gb * PRED + rank * UNITS_PER + lb;
        const float* wA = Wsel + grow0 * PRED + colbase;
        const float* wB = Wsel + grow1 * PRED + colbase;
        float4 wva[5], wvb[5];
        #pragma unroll
        for (int j = 0; j < 5; ++j) { wva[j] = *(const float4*)(wA + 4 * j); }
        #pragma unroll
        for (int j = 0; j < 5; ++j) { wvb[j] = *(const float4*)(wB + 4 * j); }
        float a00 = 0.f, a01 = 0.f, a10 = 0.f, a11 = 0.f;
        #pragma unroll
        for (int j = 0; j < 5; ++j) {
            a00 = fmaf(wva[j].x, v0[j].x, a00); a00 = fmaf(wva[j].y, v0[j].y, a00);
            a00 = fmaf(wva[j].z, v0[j].z, a00); a00 = fmaf(wva[j].w, v0[j].w, a00);
            a01 = fmaf(wva[j].x, v1[j].x, a01); a01 = fmaf(wva[j].y, v1[j].y, a01);
            a01 = fmaf(wva[j].z, v1[j].z, a01); a01 = fmaf(wva[j].w, v1[j].w, a01);
            a10 = fmaf(wvb[j].x, v0[j].x, a10); a10 = fmaf(wvb[j].y, v0[j].y, a10);
            a10 = fmaf(wvb[j].z, v0[j].z, a10); a10 = fmaf(wvb[j].w, v0[j].w, a10);
            a11 = fmaf(wvb[j].x, v1[j].x, a11); a11 = fmaf(wvb[j].y, v1[j].y, a11);
            a11 = fmaf(wvb[j].z, v1[j].z, a11); a11 = fmaf(wvb[j].w, v1[j].w, a11);
        }
        redsum4(a00, a01, a10, a11);
        if (lane == 0) {
            float bb0 = bias[grow0], bb1 = bias[grow1];
            g0[r0] = a00 + bb0; g1[r0] = a01 + bb0;
            g0[r1] = a10 + bb1; g1[r1] = a11 + bb1;
        }
    }
}

__global__ __launch_bounds__(NTHREADS, 1) __cluster_dims__(CSIZE, 1, 1)
void rnnt_greedy_kernel(const float* __restrict__ x,
                        const int*   __restrict__ out_lens,
                        const float* __restrict__ emb,
                        const float* __restrict__ Wi0, const float* __restrict__ Wh0, const float* __restrict__ b0,
                        const float* __restrict__ Wi1, const float* __restrict__ Wh1, const float* __restrict__ b1,
                        const float* __restrict__ Wj1, const float* __restrict__ bj1,
                        const float* __restrict__ Wj2, const float* __restrict__ bj2,
                        float* __restrict__ d_out, int write_lc)
{
    const int tid  = threadIdx.x;
    const int lane = tid & 31;
    const int warp = tid >> 5;

    uint32_t rank;
    asm("mov.u32 %0, %%cluster_ctarank;" : "=r"(rank));
    const int cid   = blockIdx.x / CSIZE;
    const int bbase = cid * MB;

    __shared__ __align__(16) float sh_f[MB][ENC];
    __shared__ __align__(16) float sh_e[MB][PRED];
    __shared__ __align__(16) float sh_h0[MB][PRED],  sh_h1[MB][PRED];
    __shared__ __align__(16) float sh_h0p[MB][PRED], sh_h1p[MB][PRED];
    __shared__ __align__(16) float sh_c0[MB][PRED],  sh_c1[MB][PRED];
    __shared__ __align__(16) float sh_c0p[MB][PRED], sh_c1p[MB][PRED];
    __shared__ __align__(16) float sh_g[MB][GROWS_PER];
    __shared__ __align__(16) float sh_hid[MB][JH];
    __shared__ __align__(16) float sh_logit[MB][32];
    __shared__ int sh_lt[MB][NSTEPS];
    __shared__ int s_last[MB], s_lc[MB], s_ti[MB], s_sa[MB], s_nb[MB], s_olen[MB];

    // ---- init ----
    for (int i = tid; i < MB * PRED; i += NTHREADS) {
        int m = i / PRED, j = i - m * PRED;
        sh_h0[m][j] = 0.f; sh_h1[m][j] = 0.f;
        sh_c0[m][j] = 0.f; sh_c1[m][j] = 0.f;
    }
    for (int i = tid; i < MB * NSTEPS; i += NTHREADS) {
        int m = i / NSTEPS, j = i - m * NSTEPS;
        sh_lt[m][j] = -1;
    }
    if (tid == 0) {
        #pragma unroll
        for (int m = 0; m < MB; ++m) {
            s_last[m] = -1; s_lc[m] = 0; s_ti[m] = 0; s_sa[m] = 0; s_nb[m] = 0;
            s_olen[m] = out_lens[bbase + m];
        }
    }
    __syncthreads();
    CLUSTER_SYNC();

    for (int step = 0; step < NSTEPS; ++step) {
        // ---- P0: encoder frames + embeddings (replicated per CTA) ----
        for (int i = tid; i < MB * ENC; i += NTHREADS) {
            int m = i >> 10, col = i & (ENC - 1);
            int fi = s_ti[m]; if (fi > TLEN - 1) fi = TLEN - 1;
            sh_f[m][col] = x[((bbase + m) * TLEN + fi) * ENC + col];
        }
        for (int i = tid; i < MB * PRED; i += NTHREADS) {
            int m = i / PRED, col = i - m * PRED;
            int lab = s_last[m];
            int labc = lab > (VOCAB - 2) ? (VOCAB - 2) : lab;
            sh_e[m][col] = (lab >= 0) ? emb[labc * PRED + col] : 0.0f;
        }
        __syncthreads();

        // ---- P1: layer-0 gates (40 units x 4 gates local, both batch rows) ----
        gemv_gates(Wi0, Wh0, b0, sh_e[0], sh_e[1], sh_h0[0], sh_h0[1],
                   sh_g[0], sh_g[1], (int)rank, warp, lane);
        __syncthreads();

        // ---- P2: LSTM0 nonlinearity for local slice; broadcast h0p slice ----
        if (tid < MB * UNITS_PER) {
            int m  = tid / UNITS_PER, lu = tid - m * UNITS_PER;
            int gu = rank * UNITS_PER + lu;
            float gi = sh_g[m][lu], gf = sh_g[m][UNITS_PER + lu];
            float gg = sh_g[m][2 * UNITS_PER + lu], go = sh_g[m][3 * UNITS_PER + lu];
            float c  = sigf(gf) * sh_c0[m][gu] + sigf(gi) * tanhf(gg);
            sh_c0p[m][gu] = c;
            float h  = sigf(go) * tanhf(c);
            uint32_t a = s2u(&sh_h0p[m][gu]);
            #pragma unroll
            for (int rk = 0; rk < CSIZE; ++rk) st_peer(a, rk, h);
        }
        CLUSTER_SYNC();   // S1: full h0p everywhere

        // ---- P3: layer-1 gates ----
        gemv_gates(Wi1, Wh1, b1, sh_h0p[0], sh_h0p[1], sh_h1[0], sh_h1[1],
                   sh_g[0], sh_g[1], (int)rank, warp, lane);
        __syncthreads();

        // ---- P4: LSTM1 nonlinearity; broadcast h1p slice ----
        if (tid < MB * UNITS_PER) {
            int m  = tid / UNITS_PER, lu = tid - m * UNITS_PER;
            int gu = rank * UNITS_PER + lu;
            float gi = sh_g[m][lu], gf = sh_g[m][UNITS_PER + lu];
            float gg = sh_g[m][2 * UNITS_PER + lu], go = sh_g[m][3 * UNITS_PER + lu];
            float c  = sigf(gf) * sh_c1[m][gu] + sigf(gi) * tanhf(gg);
            sh_c1p[m][gu] = c;
            float h  = sigf(go) * tanhf(c);
            uint32_t a = s2u(&sh_h1p[m][gu]);
            #pragma unroll
            for (int rk = 0; rk < CSIZE; ++rk) st_peer(a, rk, h);
        }
        CLUSTER_SYNC();   // S2: full h1p everywhere

        // ---- P5: joint hidden (64 local rows, 4 per warp, both batch rows) ----
        {
            float acc[4][2];
            #pragma unroll
            for (int rr = 0; rr < 4; ++rr) { acc[rr][0] = 0.f; acc[rr][1] = 0.f; }

            // f part: 2 passes of 512 cols (16 cols/lane)
            #pragma unroll
            for (int pass = 0; pass < 2; ++pass) {
                float4 a0[4], a1[4];
                const float* f0 = &sh_f[0][pass * 512 + 16 * lane];
                const float* f1 = &sh_f[1][pass * 512 + 16 * lane];
                #pragma unroll
                for (int j = 0; j < 4; ++j) {
                    a0[j] = *(const float4*)(f0 + 4 * j);
                    a1[j] = *(const float4*)(f1 + 4 * j);
                }
                #pragma unroll
                for (int rr = 0; rr < 4; ++rr) {
                    int jrow = rank * JROWS_PER + warp * 4 + rr;
                    const float* w = Wj1 + jrow * ZDIM + pass * 512 + 16 * lane;
                    float4 wv[4];
                    #pragma unroll
                    for (int j = 0; j < 4; ++j) wv[j] = *(const float4*)(w + 4 * j);
                    float s0 = acc[rr][0], s1 = acc[rr][1];
                    #pragma unroll
                    for (int j = 0; j < 4; ++j) {
                        s0 = fmaf(wv[j].x, a0[j].x, s0); s0 = fmaf(wv[j].y, a0[j].y, s0);
                        s0 = fmaf(wv[j].z, a0[j].z, s0); s0 = fmaf(wv[j].w, a0[j].w, s0);
                        s1 = fmaf(wv[j].x, a1[j].x, s1); s1 = fmaf(wv[j].y, a1[j].y, s1);
                        s1 = fmaf(wv[j].z, a1[j].z, s1); s1 = fmaf(wv[j].w, a1[j].w, s1);
                    }
                    acc[rr][0] = s0; acc[rr][1] = s1;
                }
            }
            // g part: h1p, 320 cols (10 cols/lane as 5 x float2)
            {
                float2 a0[5], a1[5];
                const float* p0 = &sh_h1p[0][10 * lane];
                const float* p1 = &sh_h1p[1][10 * lane];
                #pragma unroll
                for (int j = 0; j < 5; ++j) {
                    a0[j] = *(const float2*)(p0 + 2 * j);
                    a1[j] = *(const float2*)(p1 + 2 * j);
                }
                #pragma unroll
                for (int rr = 0; rr < 4; ++rr) {
                    int jrow = rank * JROWS_PER + warp * 4 + rr;
                    const float* w = Wj1 + jrow * ZDIM + ENC + 10 * lane;
                    float s0 = acc[rr][0], s1 = acc[rr][1];
                    #pragma unroll
                    for (int j = 0; j < 5; ++j) {
                        float2 wv = *(const float2*)(w + 2 * j);
                        s0 = fmaf(wv.x, a0[j].x, s0); s0 = fmaf(wv.y, a0[j].y, s0);
                        s1 = fmaf(wv.x, a1[j].x, s1); s1 = fmaf(wv.y, a1[j].y, s1);
                    }
                    acc[rr][0] = s0; acc[rr][1] = s1;
                }
            }
            // 8 reductions with ILP (2 batches of 4 chains)
            redsum4(acc[0][0], acc[0][1], acc[1][0], acc[1][1]);
            redsum4(acc[2][0], acc[2][1], acc[3][0], acc[3][1]);
            #pragma unroll
            for (int rr = 0; rr < 4; ++rr) {
                int jrow = rank * JROWS_PER + warp * 4 + rr;
                if (lane == 0) {
                    float bb = bj1[jrow];
                    float v0 = acc[rr][0] + bb; v0 = v0 > 0.f ? v0 : 0.f;
                    float v1 = acc[rr][1] + bb; v1 = v1 > 0.f ? v1 : 0.f;
                    uint32_t ad0 = s2u(&sh_hid[0][jrow]);
                    uint32_t ad1 = s2u(&sh_hid[1][jrow]);
                    #pragma unroll
                    for (int rk = 0; rk < CSIZE; ++rk) {
                        st_peer(ad0, rk, v0);
                        st_peer(ad1, rk, v1);
                    }
                }
            }
        }
        CLUSTER_SYNC();   // S3: full hid everywhere

        // ---- P6: logits (replicated: every CTA computes all 29 x 2) ----
        for (int v = warp; v < VOCAB; v += 16) {
            const float* w = Wj2 + v * JH + 16 * lane;
            float4 wv[4];
            #pragma unroll
            for (int j = 0; j < 4; ++j) wv[j] = *(const float4*)(w + 4 * j);
            float acc0 = 0.f, acc1 = 0.f, d2 = 0.f, d3 = 0.f;
            #pragma unroll
            for (int j = 0; j < 4; ++j) {
                float4 h0v = *(const float4*)&sh_hid[0][16 * lane + 4 * j];
                float4 h1v = *(const float4*)&sh_hid[1][16 * lane + 4 * j];
                acc0 = fmaf(wv[j].x, h0v.x, acc0); acc0 = fmaf(wv[j].y, h0v.y, acc0);
                acc0 = fmaf(wv[j].z, h0v.z, acc0); acc0 = fmaf(wv[j].w, h0v.w, acc0);
                acc1 = fmaf(wv[j].x, h1v.x, acc1); acc1 = fmaf(wv[j].y, h1v.y, acc1);
                acc1 = fmaf(wv[j].z, h1v.z, acc1); acc1 = fmaf(wv[j].w, h1v.w, acc1);
            }
            redsum4(acc0, acc1, d2, d3);
            if (lane == 0) {
                float bb = bj2[v];
                sh_logit[0][v] = acc0 + bb;
                sh_logit[1][v] = acc1 + bb;
            }
        }
        __syncthreads();

        // ---- P7: argmax + control, replicated identically in every CTA ----
        if (tid == 0) {
            #pragma unroll
            for (int m = 0; m < MB; ++m) {
                float best = sh_logit[m][0]; int k = 0;
                #pragma unroll
                for (int v = 1; v < VOCAB; ++v) {
                    float lv = sh_logit[m][v];
                    if (lv > best) { best = lv; k = v; }
                }
                int ti = s_ti[m], sa = s_sa[m], lc = s_lc[m];
                bool blk = (k == BLANK);
                if (blk) ti += 1;
                bool done = (ti >= s_olen[m]);
                if (blk) sa = 0;
                bool nb = !(done || blk);
                if (nb) {
                    lc += 1;
                    if (lc <= NSTEPS - 1) sh_lt[m][lc] += (k + 1);  // JAX scatter: OOB dropped
                    sa += 1;
                }
                {
                    int pos = lc; if (pos > NSTEPS - 1) pos = NSTEPS - 1;
                    s_last[m] = sh_lt[m][pos];                       // JAX gather: clamp
                }
                if (sa >= MAXSYM) { ti += 1; sa = 0; }
                s_ti[m] = ti; s_sa[m] = sa; s_lc[m] = lc; s_nb[m] = nb ? 1 : 0;
            }
        }
        __syncthreads();

        // ---- P8: conditional state commit (h full, c local slice) ----
        for (int i = tid; i < MB * PRED; i += NTHREADS) {
            int m = i / PRED, j = i - m * PRED;
            if (s_nb[m]) { sh_h0[m][j] = sh_h0p[m][j]; sh_h1[m][j] = sh_h1p[m][j]; }
        }
        if (tid < MB * UNITS_PER) {
            int m  = tid / UNITS_PER, lu = tid - m * UNITS_PER;
            int gu = rank * UNITS_PER + lu;
            if (s_nb[m]) { sh_c0[m][gu] = sh_c0p[m][gu]; sh_c1[m][gu] = sh_c1p[m][gu]; }
        }
        CLUSTER_SYNC();   // S4: protects h0p/h1p against next step's peer writes
    }

    // ---- output (rank 0 of each cluster): lt as float32, then lc ----
    if (rank == 0) {
        for (int m = 0; m < MB; ++m) {
            for (int i = tid; i < NSTEPS; i += NTHREADS)
                d_out[(bbase + m) * NSTEPS + i] = (float)sh_lt[m][i];
        }
        if (tid == 0 && write_lc) {
            d_out[BATCH * NSTEPS + bbase + 0] = (float)s_lc[0];
            d_out[BATCH * NSTEPS + bbase + 1] = (float)s_lc[1];
        }
    }
}

extern "C" void kernel_launch(void* const* d_in, const int* in_sizes, int n_in,
                              void* d_out, int out_size) {
    const float* x        = (const float*)d_in[0];
    const int*   out_lens = (const int*)  d_in[1];
    const float* emb      = (const float*)d_in[2];
    const float* Wi0      = (const float*)d_in[3];
    const float* Wh0      = (const float*)d_in[4];
    const float* b0       = (const float*)d_in[5];
    const float* Wi1      = (const float*)d_in[6];
    const float* Wh1      = (const float*)d_in[7];
    const float* b1       = (const float*)d_in[8];
    const float* Wj1      = (const float*)d_in[9];
    const float* bj1      = (const float*)d_in[10];
    const float* Wj2      = (const float*)d_in[11];
    const float* bj2      = (const float*)d_in[12];

    int write_lc = (out_size >= BATCH * NSTEPS + BATCH) ? 1 : 0;

    rnnt_greedy_kernel<<<(BATCH / MB) * CSIZE, NTHREADS>>>(
        x, out_lens, emb,
        Wi0, Wh0, b0, Wi1, Wh1, b1,
        Wj1, bj1, Wj2, bj2,
        (float*)d_out, write_lc);
}

// round 7
// speedup vs baseline: 1.2341x; 1.2341x over previous
#include <cuda_runtime.h>
#include <math.h>
#include <stdint.h>

#define ENC 1024
#define PRED 320
#define JH 512
#define VOCAB 29
#define BLANK 28
#define MAXSYM 6
#define BATCH 32
#define TLEN 48
#define NSTEPS 288
#define ZDIM 1344
#define CSIZE 4                    // CTAs per cluster  (R6's 8 regressed; back to 4)
#define MB 2                       // batch rows per cluster
#define NTHREADS 512
#define UNITS_PER (PRED / CSIZE)   // 80 LSTM units per CTA
#define GROWS_PER (4 * UNITS_PER)  // 320 gate rows per CTA
#define JROWS_PER (JH / CSIZE)     // 128 joint rows per CTA

#define CLUSTER_SYNC() do { \
    asm volatile("barrier.cluster.arrive.aligned;" ::: "memory"); \
    asm volatile("barrier.cluster.wait.aligned;"   ::: "memory"); \
} while (0)

__device__ __forceinline__ float sigf(float v) { return 1.0f / (1.0f + expf(-v)); }

__device__ __forceinline__ uint32_t s2u(const void* p) {
    return (uint32_t)__cvta_generic_to_shared((void*)p);
}

// store v into the SMEM copy of `addr` in cluster CTA `rank`
__device__ __forceinline__ void st_peer(uint32_t addr, int rank, float v) {
    uint32_t pa;
    asm volatile("mapa.shared::cluster.u32 %0, %1, %2;" : "=r"(pa) : "r"(addr), "r"(rank));
    asm volatile("st.shared::cluster.f32 [%0], %1;" :: "r"(pa), "f"(v));
}

// 4 interleaved shfl-down reductions (independent chains -> ILP hides shfl latency)
__device__ __forceinline__ void redsum4(float& a, float& b, float& c, float& d) {
    #pragma unroll
    for (int o = 16; o > 0; o >>= 1) {
        a += __shfl_down_sync(0xffffffffu, a, o);
        b += __shfl_down_sync(0xffffffffu, b, o);
        c += __shfl_down_sync(0xffffffffu, c, o);
        d += __shfl_down_sync(0xffffffffu, d, o);
    }
}

// Gate GEMV: 320 local rows (4 gates x 80 units), width 640 = [A(320);B(320)], 2 batch rows.
// lanes 0-15 cover A cols [20*lane,+20); lanes 16-31 cover B cols [20*(lane-16),+20).
// 20 rows/warp processed as 10 pairs: 10 independent LDG.128 in flight,
// 4 interleaved shfl-reduction chains per pair.
__device__ __forceinline__ void gemv_gates(
    const float* __restrict__ Wi, const float* __restrict__ Wh, const float* __restrict__ bias,
    const float* sA0, const float* sA1,
    const float* sB0, const float* sB1,
    float* g0, float* g1,
    int rank, int warp, int lane)
{
    const int  colbase = 20 * (lane & 15);
    const bool loA = (lane < 16);
    const float* a0 = (loA ? sA0 : sB0) + colbase;
    const float* a1 = (loA ? sA1 : sB1) + colbase;
    float4 v0[5], v1[5];
    #pragma unroll
    for (int j = 0; j < 5; ++j) {
        v0[j] = *(const float4*)(a0 + 4 * j);
        v1[j] = *(const float4*)(a1 + 4 * j);
    }
    const float* Wsel = loA ? Wi : Wh;
    #pragma unroll
    for (int pp = 0; pp < 10; ++pp) {                // 20 rows/warp as 10 pairs
        int r0 = warp * 20 + 2 * pp;
        int r1 = r0 + 1;
        int ga = r0 / UNITS_PER, la = r0 - ga * UNITS_PER;
        int gb = r1 / UNITS_PER, lb = r1 - gb * UNITS_PER;
        int grow0 = ga * PRED + rank * UNITS_PER + la;
        int grow1 = gb * PRED + rank * UNITS_PER + lb;
        const float* wA = Wsel + grow0 * PRED + colbase;
        const float* wB = Wsel + grow1 * PRED + colbase;
        float4 wva[5], wvb[5];
        #pragma unroll
        for (int j = 0; j < 5; ++j) { wva[j] = *(const float4*)(wA + 4 * j); }
        #pragma unroll
        for (int j = 0; j < 5; ++j) { wvb[j] = *(const float4*)(wB + 4 * j); }
        float a00 = 0.f, a01 = 0.f, a10 = 0.f, a11 = 0.f;
        #pragma unroll
        for (int j = 0; j < 5; ++j) {
            a00 = fmaf(wva[j].x, v0[j].x, a00); a00 = fmaf(wva[j].y, v0[j].y, a00);
            a00 = fmaf(wva[j].z, v0[j].z, a00); a00 = fmaf(wva[j].w, v0[j].w, a00);
            a01 = fmaf(wva[j].x, v1[j].x, a01); a01 = fmaf(wva[j].y, v1[j].y, a01);
            a01 = fmaf(wva[j].z, v1[j].z, a01); a01 = fmaf(wva[j].w, v1[j].w, a01);
            a10 = fmaf(wvb[j].x, v0[j].x, a10); a10 = fmaf(wvb[j].y, v0[j].y, a10);
            a10 = fmaf(wvb[j].z, v0[j].z, a10); a10 = fmaf(wvb[j].w, v0[j].w, a10);
            a11 = fmaf(wvb[j].x, v1[j].x, a11); a11 = fmaf(wvb[j].y, v1[j].y, a11);
            a11 = fmaf(wvb[j].z, v1[j].z, a11); a11 = fmaf(wvb[j].w, v1[j].w, a11);
        }
        redsum4(a00, a01, a10, a11);
        if (lane == 0) {
            float bb0 = bias[grow0], bb1 = bias[grow1];
            g0[r0] = a00 + bb0; g1[r0] = a01 + bb0;
            g0[r1] = a10 + bb1; g1[r1] = a11 + bb1;
        }
    }
}

__global__ __launch_bounds__(NTHREADS, 1) __cluster_dims__(CSIZE, 1, 1)
void rnnt_greedy_kernel(const float* __restrict__ x,
                        const int*   __restrict__ out_lens,
                        const float* __restrict__ emb,
                        const float* __restrict__ Wi0, const float* __restrict__ Wh0, const float* __restrict__ b0,
                        const float* __restrict__ Wi1, const float* __restrict__ Wh1, const float* __restrict__ b1,
                        const float* __restrict__ Wj1, const float* __restrict__ bj1,
                        const float* __restrict__ Wj2, const float* __restrict__ bj2,
                        float* __restrict__ d_out, int write_lc)
{
    const int tid  = threadIdx.x;
    const int lane = tid & 31;
    const int warp = tid >> 5;

    uint32_t rank;
    asm("mov.u32 %0, %%cluster_ctarank;" : "=r"(rank));
    const int cid   = blockIdx.x / CSIZE;
    const int bbase = cid * MB;

    __shared__ __align__(16) float sh_f[MB][ENC];
    __shared__ __align__(16) float sh_e[MB][PRED];
    __shared__ __align__(16) float sh_h0[MB][PRED],  sh_h1[MB][PRED];
    __shared__ __align__(16) float sh_h0p[MB][PRED], sh_h1p[MB][PRED];
    __shared__ __align__(16) float sh_c0[MB][PRED],  sh_c1[MB][PRED];
    __shared__ __align__(16) float sh_c0p[MB][PRED], sh_c1p[MB][PRED];
    __shared__ __align__(16) float sh_g[MB][GROWS_PER];
    __shared__ __align__(16) float sh_hid[MB][JH];
    __shared__ __align__(16) float sh_logit[MB][32];
    __shared__ int sh_lt[MB][NSTEPS];
    __shared__ int s_last[MB], s_lc[MB], s_ti[MB], s_sa[MB], s_nb[MB], s_olen[MB];

    // ---- init ----
    for (int i = tid; i < MB * PRED; i += NTHREADS) {
        int m = i / PRED, j = i - m * PRED;
        sh_h0[m][j] = 0.f; sh_h1[m][j] = 0.f;
        sh_c0[m][j] = 0.f; sh_c1[m][j] = 0.f;
    }
    for (int i = tid; i < MB * NSTEPS; i += NTHREADS) {
        int m = i / NSTEPS, j = i - m * NSTEPS;
        sh_lt[m][j] = -1;
    }
    if (tid == 0) {
        #pragma unroll
        for (int m = 0; m < MB; ++m) {
            s_last[m] = -1; s_lc[m] = 0; s_ti[m] = 0; s_sa[m] = 0; s_nb[m] = 0;
            s_olen[m] = out_lens[bbase + m];
        }
    }
    __syncthreads();
    CLUSTER_SYNC();

    for (int step = 0; step < NSTEPS; ++step) {
        // ---- P0: encoder frames + embeddings (replicated per CTA) ----
        for (int i = tid; i < MB * ENC; i += NTHREADS) {
            int m = i >> 10, col = i & (ENC - 1);
            int fi = s_ti[m]; if (fi > TLEN - 1) fi = TLEN - 1;
            sh_f[m][col] = x[((bbase + m) * TLEN + fi) * ENC + col];
        }
        for (int i = tid; i < MB * PRED; i += NTHREADS) {
            int m = i / PRED, col = i - m * PRED;
            int lab = s_last[m];
            int labc = lab > (VOCAB - 2) ? (VOCAB - 2) : lab;
            sh_e[m][col] = (lab >= 0) ? emb[labc * PRED + col] : 0.0f;
        }
        __syncthreads();

        // ---- P1: layer-0 gates (80 units x 4 gates local, both batch rows) ----
        gemv_gates(Wi0, Wh0, b0, sh_e[0], sh_e[1], sh_h0[0], sh_h0[1],
                   sh_g[0], sh_g[1], (int)rank, warp, lane);
        __syncthreads();

        // ---- P2: LSTM0 nonlinearity for local slice; broadcast h0p slice ----
        if (tid < MB * UNITS_PER) {
            int m  = tid / UNITS_PER, lu = tid - m * UNITS_PER;
            int gu = rank * UNITS_PER + lu;
            float gi = sh_g[m][lu], gf = sh_g[m][UNITS_PER + lu];
            float gg = sh_g[m][2 * UNITS_PER + lu], go = sh_g[m][3 * UNITS_PER + lu];
            float c  = sigf(gf) * sh_c0[m][gu] + sigf(gi) * tanhf(gg);
            sh_c0p[m][gu] = c;
            float h  = sigf(go) * tanhf(c);
            uint32_t a = s2u(&sh_h0p[m][gu]);
            #pragma unroll
            for (int rk = 0; rk < CSIZE; ++rk) st_peer(a, rk, h);
        }
        CLUSTER_SYNC();   // S1: full h0p everywhere

        // ---- P3: layer-1 gates ----
        gemv_gates(Wi1, Wh1, b1, sh_h0p[0], sh_h0p[1], sh_h1[0], sh_h1[1],
                   sh_g[0], sh_g[1], (int)rank, warp, lane);
        __syncthreads();

        // ---- P4: LSTM1 nonlinearity; broadcast h1p slice ----
        if (tid < MB * UNITS_PER) {
            int m  = tid / UNITS_PER, lu = tid - m * UNITS_PER;
            int gu = rank * UNITS_PER + lu;
            float gi = sh_g[m][lu], gf = sh_g[m][UNITS_PER + lu];
            float gg = sh_g[m][2 * UNITS_PER + lu], go = sh_g[m][3 * UNITS_PER + lu];
            float c  = sigf(gf) * sh_c1[m][gu] + sigf(gi) * tanhf(gg);
            sh_c1p[m][gu] = c;
            float h  = sigf(go) * tanhf(c);
            uint32_t a = s2u(&sh_h1p[m][gu]);
            #pragma unroll
            for (int rk = 0; rk < CSIZE; ++rk) st_peer(a, rk, h);
        }
        CLUSTER_SYNC();   // S2: full h1p everywhere

        // ---- P5: joint hidden (128 local rows, 8 per warp, both batch rows) ----
        {
            float acc[8][2];
            #pragma unroll
            for (int rr = 0; rr < 8; ++rr) { acc[rr][0] = 0.f; acc[rr][1] = 0.f; }

            // f part: 2 passes of 512 cols (16 cols/lane)
            #pragma unroll
            for (int pass = 0; pass < 2; ++pass) {
                float4 a0[4], a1[4];
                const float* f0 = &sh_f[0][pass * 512 + 16 * lane];
                const float* f1 = &sh_f[1][pass * 512 + 16 * lane];
                #pragma unroll
                for (int j = 0; j < 4; ++j) {
                    a0[j] = *(const float4*)(f0 + 4 * j);
                    a1[j] = *(const float4*)(f1 + 4 * j);
                }
                #pragma unroll
                for (int rr = 0; rr < 8; ++rr) {
                    int jrow = rank * JROWS_PER + warp * 8 + rr;
                    const float* w = Wj1 + jrow * ZDIM + pass * 512 + 16 * lane;
                    float4 wv[4];
                    #pragma unroll
                    for (int j = 0; j < 4; ++j) wv[j] = *(const float4*)(w + 4 * j);
                    float s0 = acc[rr][0], s1 = acc[rr][1];
                    #pragma unroll
                    for (int j = 0; j < 4; ++j) {
                        s0 = fmaf(wv[j].x, a0[j].x, s0); s0 = fmaf(wv[j].y, a0[j].y, s0);
                        s0 = fmaf(wv[j].z, a0[j].z, s0); s0 = fmaf(wv[j].w, a0[j].w, s0);
                        s1 = fmaf(wv[j].x, a1[j].x, s1); s1 = fmaf(wv[j].y, a1[j].y, s1);
                        s1 = fmaf(wv[j].z, a1[j].z, s1); s1 = fmaf(wv[j].w, a1[j].w, s1);
                    }
                    acc[rr][0] = s0; acc[rr][1] = s1;
                }
            }
            // g part: h1p, 320 cols (10 cols/lane as 5 x float2)
            {
                float2 a0[5], a1[5];
                const float* p0 = &sh_h1p[0][10 * lane];
                const float* p1 = &sh_h1p[1][10 * lane];
                #pragma unroll
                for (int j = 0; j < 5; ++j) {
                    a0[j] = *(const float2*)(p0 + 2 * j);
                    a1[j] = *(const float2*)(p1 + 2 * j);
                }
                #pragma unroll
                for (int rr = 0; rr < 8; ++rr) {
                    int jrow = rank * JROWS_PER + warp * 8 + rr;
                    const float* w = Wj1 + jrow * ZDIM + ENC + 10 * lane;
                    float s0 = acc[rr][0], s1 = acc[rr][1];
                    #pragma unroll
                    for (int j = 0; j < 5; ++j) {
                        float2 wv = *(const float2*)(w + 2 * j);
                        s0 = fmaf(wv.x, a0[j].x, s0); s0 = fmaf(wv.y, a0[j].y, s0);
                        s1 = fmaf(wv.x, a1[j].x, s1); s1 = fmaf(wv.y, a1[j].y, s1);
                    }
                    acc[rr][0] = s0; acc[rr][1] = s1;
                }
            }
            // 16 reductions with ILP (4 batches of 4 interleaved chains)
            redsum4(acc[0][0], acc[0][1], acc[1][0], acc[1][1]);
            redsum4(acc[2][0], acc[2][1], acc[3][0], acc[3][1]);
            redsum4(acc[4][0], acc[4][1], acc[5][0], acc[5][1]);
            redsum4(acc[6][0], acc[6][1], acc[7][0], acc[7][1]);
            #pragma unroll
            for (int rr = 0; rr < 8; ++rr) {
                int jrow = rank * JROWS_PER + warp * 8 + rr;
                if (lane == 0) {
                    float bb = bj1[jrow];
                    float v0 = acc[rr][0] + bb; v0 = v0 > 0.f ? v0 : 0.f;
                    float v1 = acc[rr][1] + bb; v1 = v1 > 0.f ? v1 : 0.f;
                    uint32_t ad0 = s2u(&sh_hid[0][jrow]);
                    uint32_t ad1 = s2u(&sh_hid[1][jrow]);
                    #pragma unroll
                    for (int rk = 0; rk < CSIZE; ++rk) {
                        st_peer(ad0, rk, v0);
                        st_peer(ad1, rk, v1);
                    }
                }
            }
        }
        CLUSTER_SYNC();   // S3: full hid everywhere

        // ---- P6: logits (replicated: every CTA computes all 29 x 2) ----
        for (int v = warp; v < VOCAB; v += 16) {
            const float* w = Wj2 + v * JH + 16 * lane;
            float4 wv[4];
            #pragma unroll
            for (int j = 0; j < 4; ++j) wv[j] = *(const float4*)(w + 4 * j);
            float acc0 = 0.f, acc1 = 0.f, d2 = 0.f, d3 = 0.f;
            #pragma unroll
            for (int j = 0; j < 4; ++j) {
                float4 h0v = *(const float4*)&sh_hid[0][16 * lane + 4 * j];
                float4 h1v = *(const float4*)&sh_hid[1][16 * lane + 4 * j];
                acc0 = fmaf(wv[j].x, h0v.x, acc0); acc0 = fmaf(wv[j].y, h0v.y, acc0);
                acc0 = fmaf(wv[j].z, h0v.z, acc0); acc0 = fmaf(wv[j].w, h0v.w, acc0);
                acc1 = fmaf(wv[j].x, h1v.x, acc1); acc1 = fmaf(wv[j].y, h1v.y, acc1);
                acc1 = fmaf(wv[j].z, h1v.z, acc1); acc1 = fmaf(wv[j].w, h1v.w, acc1);
            }
            redsum4(acc0, acc1, d2, d3);
            if (lane == 0) {
                float bb = bj2[v];
                sh_logit[0][v] = acc0 + bb;
                sh_logit[1][v] = acc1 + bb;
            }
        }
        __syncthreads();

        // ---- P7: argmax + control, replicated identically in every CTA ----
        if (tid == 0) {
            #pragma unroll
            for (int m = 0; m < MB; ++m) {
                float best = sh_logit[m][0]; int k = 0;
                #pragma unroll
                for (int v = 1; v < VOCAB; ++v) {
                    float lv = sh_logit[m][v];
                    if (lv > best) { best = lv; k = v; }
                }
                int ti = s_ti[m], sa = s_sa[m], lc = s_lc[m];
                bool blk = (k == BLANK);
                if (blk) ti += 1;
                bool done = (ti >= s_olen[m]);
                if (blk) sa = 0;
                bool nb = !(done || blk);
                if (nb) {
                    lc += 1;
                    if (lc <= NSTEPS - 1) sh_lt[m][lc] += (k + 1);  // JAX scatter: OOB dropped
                    sa += 1;
                }
                {
                    int pos = lc; if (pos > NSTEPS - 1) pos = NSTEPS - 1;
                    s_last[m] = sh_lt[m][pos];                       // JAX gather: clamp
                }
                if (sa >= MAXSYM) { ti += 1; sa = 0; }
                s_ti[m] = ti; s_sa[m] = sa; s_lc[m] = lc; s_nb[m] = nb ? 1 : 0;
            }
        }
        __syncthreads();

        // ---- P8: conditional state commit (h full, c local slice) ----
        for (int i = tid; i < MB * PRED; i += NTHREADS) {
            int m = i / PRED, j = i - m * PRED;
            if (s_nb[m]) { sh_h0[m][j] = sh_h0p[m][j]; sh_h1[m][j] = sh_h1p[m][j]; }
        }
        if (tid < MB * UNITS_PER) {
            int m  = tid / UNITS_PER, lu = tid - m * UNITS_PER;
            int gu = rank * UNITS_PER + lu;
            if (s_nb[m]) { sh_c0[m][gu] = sh_c0p[m][gu]; sh_c1[m][gu] = sh_c1p[m][gu]; }
        }
        CLUSTER_SYNC();   // S4: protects h0p/h1p against next step's peer writes
    }

    // ---- output (rank 0 of each cluster): lt as float32, then lc ----
    if (rank == 0) {
        for (int m = 0; m < MB; ++m) {
            for (int i = tid; i < NSTEPS; i += NTHREADS)
                d_out[(bbase + m) * NSTEPS + i] = (float)sh_lt[m][i];
        }
        if (tid == 0 && write_lc) {
            d_out[BATCH * NSTEPS + bbase + 0] = (float)s_lc[0];
            d_out[BATCH * NSTEPS + bbase + 1] = (float)s_lc[1];
        }
    }
}

extern "C" void kernel_launch(void* const* d_in, const int* in_sizes, int n_in,
                              void* d_out, int out_size) {
    const float* x        = (const float*)d_in[0];
    const int*   out_lens = (const int*)  d_in[1];
    const float* emb      = (const float*)d_in[2];
    const float* Wi0      = (const float*)d_in[3];
    const float* Wh0      = (const float*)d_in[4];
    const float* b0       = (const float*)d_in[5];
    const float* Wi1      = (const float*)d_in[6];
    const float* Wh1      = (const float*)d_in[7];
    const float* b1       = (const float*)d_in[8];
    const float* Wj1      = (const float*)d_in[9];
    const float* bj1      = (const float*)d_in[10];
    const float* Wj2      = (const float*)d_in[11];
    const float* bj2      = (const float*)d_in[12];

    int write_lc = (out_size >= BATCH * NSTEPS + BATCH) ? 1 : 0;

    rnnt_greedy_kernel<<<(BATCH / MB) * CSIZE, NTHREADS>>>(
        x, out_lens, emb,
        Wi0, Wh0, b0, Wi1, Wh1, b1,
        Wj1, bj1, Wj2, bj2,
        (float*)d_out, write_lc);
}

// round 9
// speedup vs baseline: 1.4456x; 1.1714x over previous
#include <cuda_runtime.h>
#include <math.h>
#include <stdint.h>

#define ENC 1024
#define PRED 320
#define JH 512
#define VOCAB 29
#define BLANK 28
#define MAXSYM 6
#define BATCH 32
#define TLEN 48
#define NSTEPS 288
#define ZDIM 1344
#define CSIZE 4                    // CTAs per cluster
#define MB 2                       // batch rows per cluster
#define NTHREADS 512
#define UNITS_PER (PRED / CSIZE)   // 80 LSTM units per CTA
#define GROWS_PER (4 * UNITS_PER)  // 320 gate rows per CTA
#define JROWS_PER (JH / CSIZE)     // 128 joint rows per CTA

// NOTE: cluster barriers are ALWAYS executed by every thread on every step.
// Early termination is a uniform skip-flag on the compute phases only —
// the barrier count is compile-time fixed (no data-dependent break).
#define CLUSTER_SYNC() do { \
    asm volatile("barrier.cluster.arrive.aligned;" ::: "memory"); \
    asm volatile("barrier.cluster.wait.aligned;"   ::: "memory"); \
} while (0)

__device__ __forceinline__ float sigf(float v) { return 1.0f / (1.0f + expf(-v)); }

__device__ __forceinline__ float wredsum(float v) {
    #pragma unroll
    for (int o = 16; o > 0; o >>= 1) v += __shfl_down_sync(0xffffffffu, v, o);
    return v;
}

__device__ __forceinline__ uint32_t s2u(const void* p) {
    return (uint32_t)__cvta_generic_to_shared((void*)p);
}

// store v into the SMEM copy of `addr` in cluster CTA `rank`
__device__ __forceinline__ void st_peer(uint32_t addr, int rank, float v) {
    uint32_t pa;
    asm volatile("mapa.shared::cluster.u32 %0, %1, %2;" : "=r"(pa) : "r"(addr), "r"(rank));
    asm volatile("st.shared::cluster.f32 [%0], %1;" :: "r"(pa), "f"(v));
}

// Gate GEMV: 320 local rows (4 gates x 80 units), width 640 = [A(320);B(320)], 2 batch rows fused.
// lanes 0-15 cover A cols [20*lane, +20); lanes 16-31 cover B cols [20*(lane-16), +20).
// (R5 exact form — measured fastest; R6/R7 ILP variants regressed.)
__device__ __forceinline__ void gemv_gates(
    const float* __restrict__ Wi, const float* __restrict__ Wh, const float* __restrict__ bias,
    const float* sA0, const float* sA1,
    const float* sB0, const float* sB1,
    float* g0, float* g1,
    int rank, int warp, int lane)
{
    const int  colbase = 20 * (lane & 15);
    const bool loA = (lane < 16);
    const float* a0 = (loA ? sA0 : sB0) + colbase;
    const float* a1 = (loA ? sA1 : sB1) + colbase;
    float4 v0[5], v1[5];
    #pragma unroll
    for (int j = 0; j < 5; ++j) {
        v0[j] = *(const float4*)(a0 + 4 * j);
        v1[j] = *(const float4*)(a1 + 4 * j);
    }
    const float* Wsel = loA ? Wi : Wh;
    for (int rr = 0; rr < 20; ++rr) {
        int r  = warp * 20 + rr;
        int g  = r / UNITS_PER;
        int lu = r - g * UNITS_PER;
        int grow = g * PRED + rank * UNITS_PER + lu;
        const float* w = Wsel + grow * PRED + colbase;
        float acc0 = 0.f, acc1 = 0.f;
        #pragma unroll
        for (int j = 0; j < 5; ++j) {
            float4 wv = *(const float4*)(w + 4 * j);
            acc0 = fmaf(wv.x, v0[j].x, acc0); acc0 = fmaf(wv.y, v0[j].y, acc0);
            acc0 = fmaf(wv.z, v0[j].z, acc0); acc0 = fmaf(wv.w, v0[j].w, acc0);
            acc1 = fmaf(wv.x, v1[j].x, acc1); acc1 = fmaf(wv.y, v1[j].y, acc1);
            acc1 = fmaf(wv.z, v1[j].z, acc1); acc1 = fmaf(wv.w, v1[j].w, acc1);
        }
        acc0 = wredsum(acc0);
        acc1 = wredsum(acc1);
        if (lane == 0) {
            float bb = bias[grow];
            g0[r] = acc0 + bb;
            g1[r] = acc1 + bb;
        }
    }
}

__global__ __launch_bounds__(NTHREADS, 1) __cluster_dims__(CSIZE, 1, 1)
void rnnt_greedy_kernel(const float* __restrict__ x,
                        const int*   __restrict__ out_lens,
                        const float* __restrict__ emb,
                        const float* __restrict__ Wi0, const float* __restrict__ Wh0, const float* __restrict__ b0,
                        const float* __restrict__ Wi1, const float* __restrict__ Wh1, const float* __restrict__ b1,
                        const float* __restrict__ Wj1, const float* __restrict__ bj1,
                        const float* __restrict__ Wj2, const float* __restrict__ bj2,
                        float* __restrict__ d_out, int write_lc)
{
    const int tid  = threadIdx.x;
    const int lane = tid & 31;
    const int warp = tid >> 5;

    uint32_t rank;
    asm("mov.u32 %0, %%cluster_ctarank;" : "=r"(rank));
    const int cid   = blockIdx.x / CSIZE;
    const int bbase = cid * MB;

    __shared__ __align__(16) float sh_f[MB][ENC];
    __shared__ __align__(16) float sh_e[MB][PRED];
    __shared__ __align__(16) float sh_h0[MB][PRED],  sh_h1[MB][PRED];
    __shared__ __align__(16) float sh_h0p[MB][PRED], sh_h1p[MB][PRED];
    __shared__ __align__(16) float sh_c0[MB][PRED],  sh_c1[MB][PRED];
    __shared__ __align__(16) float sh_c0p[MB][PRED], sh_c1p[MB][PRED];
    __shared__ __align__(16) float sh_g[MB][GROWS_PER];
    __shared__ __align__(16) float sh_hid[MB][JH];
    __shared__ __align__(16) float sh_logit[MB][32];
    __shared__ int sh_lt[MB][NSTEPS];
    __shared__ int s_last[MB], s_lc[MB], s_ti[MB], s_sa[MB], s_nb[MB], s_olen[MB];
    __shared__ int s_alldone;

    // ---- init ----
    for (int i = tid; i < MB * PRED; i += NTHREADS) {
        int m = i / PRED, j = i - m * PRED;
        sh_h0[m][j] = 0.f; sh_h1[m][j] = 0.f;
        sh_c0[m][j] = 0.f; sh_c1[m][j] = 0.f;
    }
    for (int i = tid; i < MB * NSTEPS; i += NTHREADS) {
        int m = i / NSTEPS, j = i - m * NSTEPS;
        sh_lt[m][j] = -1;
    }
    if (tid == 0) {
        #pragma unroll
        for (int m = 0; m < MB; ++m) {
            s_last[m] = -1; s_lc[m] = 0; s_ti[m] = 0; s_sa[m] = 0; s_nb[m] = 0;
            s_olen[m] = out_lens[bbase + m];
        }
        s_alldone = 0;
    }
    __syncthreads();
    CLUSTER_SYNC();

    for (int step = 0; step < NSTEPS; ++step) {
        // Uniform skip flag. Last write was previous step's P7 (tid 0), separated
        // from this read by the __syncthreads after P7 — no race. Once a cluster's
        // rows are all permanently done, outputs are frozen, so the remaining
        // steps are output-neutral and can be skipped compute-wise. All barriers
        // below execute unconditionally on every step.
        const bool active = (s_alldone == 0);

        // ---- P0: encoder frames + embeddings (replicated per CTA) ----
        if (active) {
            for (int i = tid; i < MB * ENC; i += NTHREADS) {
                int m = i >> 10, col = i & (ENC - 1);
                int fi = s_ti[m]; if (fi > TLEN - 1) fi = TLEN - 1;
                sh_f[m][col] = x[((bbase + m) * TLEN + fi) * ENC + col];
            }
            for (int i = tid; i < MB * PRED; i += NTHREADS) {
                int m = i / PRED, col = i - m * PRED;
                int lab = s_last[m];
                int labc = lab > (VOCAB - 2) ? (VOCAB - 2) : lab;
                sh_e[m][col] = (lab >= 0) ? emb[labc * PRED + col] : 0.0f;
            }
        }
        __syncthreads();

        // ---- P1: layer-0 gates ----
        if (active) {
            gemv_gates(Wi0, Wh0, b0, sh_e[0], sh_e[1], sh_h0[0], sh_h0[1],
                       sh_g[0], sh_g[1], (int)rank, warp, lane);
        }
        __syncthreads();

        // ---- P2: LSTM0 nonlinearity for local slice; broadcast h0p slice ----
        if (active && tid < MB * UNITS_PER) {
            int m  = tid / UNITS_PER, lu = tid - m * UNITS_PER;
            int gu = rank * UNITS_PER + lu;
            float gi = sh_g[m][lu], gf = sh_g[m][UNITS_PER + lu];
            float gg = sh_g[m][2 * UNITS_PER + lu], go = sh_g[m][3 * UNITS_PER + lu];
            float c  = sigf(gf) * sh_c0[m][gu] + sigf(gi) * tanhf(gg);
            sh_c0p[m][gu] = c;
            float h  = sigf(go) * tanhf(c);
            uint32_t a = s2u(&sh_h0p[m][gu]);
            #pragma unroll
            for (int rk = 0; rk < CSIZE; ++rk) st_peer(a, rk, h);
        }
        CLUSTER_SYNC();   // S1: full h0p assembled everywhere

        // ---- P3: layer-1 gates ----
        if (active) {
            gemv_gates(Wi1, Wh1, b1, sh_h0p[0], sh_h0p[1], sh_h1[0], sh_h1[1],
                       sh_g[0], sh_g[1], (int)rank, warp, lane);
        }
        __syncthreads();

        // ---- P4: LSTM1 nonlinearity; broadcast h1p slice ----
        if (active && tid < MB * UNITS_PER) {
            int m  = tid / UNITS_PER, lu = tid - m * UNITS_PER;
            int gu = rank * UNITS_PER + lu;
            float gi = sh_g[m][lu], gf = sh_g[m][UNITS_PER + lu];
            float gg = sh_g[m][2 * UNITS_PER + lu], go = sh_g[m][3 * UNITS_PER + lu];
            float c  = sigf(gf) * sh_c1[m][gu] + sigf(gi) * tanhf(gg);
            sh_c1p[m][gu] = c;
            float h  = sigf(go) * tanhf(c);
            uint32_t a = s2u(&sh_h1p[m][gu]);
            #pragma unroll
            for (int rk = 0; rk < CSIZE; ++rk) st_peer(a, rk, h);
        }
        CLUSTER_SYNC();   // S2: full h1p assembled everywhere

        // ---- P5: joint hidden (this CTA's 128 rows, both batch rows) ----
        if (active) {
            float acc[8][2];
            #pragma unroll
            for (int rr = 0; rr < 8; ++rr) { acc[rr][0] = 0.f; acc[rr][1] = 0.f; }

            // f part: 2 passes of 512 cols (16 cols/lane each)
            #pragma unroll
            for (int pass = 0; pass < 2; ++pass) {
                float4 a0[4], a1[4];
                const float* f0 = &sh_f[0][pass * 512 + 16 * lane];
                const float* f1 = &sh_f[1][pass * 512 + 16 * lane];
                #pragma unroll
                for (int j = 0; j < 4; ++j) {
                    a0[j] = *(const float4*)(f0 + 4 * j);
                    a1[j] = *(const float4*)(f1 + 4 * j);
                }
                #pragma unroll
                for (int rr = 0; rr < 8; ++rr) {
                    int jrow = rank * JROWS_PER + warp * 8 + rr;
                    const float* w = Wj1 + jrow * ZDIM + pass * 512 + 16 * lane;
                    float s0 = acc[rr][0], s1 = acc[rr][1];
                    #pragma unroll
                    for (int j = 0; j < 4; ++j) {
                        float4 wv = *(const float4*)(w + 4 * j);
                        s0 = fmaf(wv.x, a0[j].x, s0); s0 = fmaf(wv.y, a0[j].y, s0);
                        s0 = fmaf(wv.z, a0[j].z, s0); s0 = fmaf(wv.w, a0[j].w, s0);
                        s1 = fmaf(wv.x, a1[j].x, s1); s1 = fmaf(wv.y, a1[j].y, s1);
                        s1 = fmaf(wv.z, a1[j].z, s1); s1 = fmaf(wv.w, a1[j].w, s1);
                    }
                    acc[rr][0] = s0; acc[rr][1] = s1;
                }
            }
            // g part: h1p, 320 cols (10 cols/lane as 5 x float2)
            {
                float2 a0[5], a1[5];
                const float* p0 = &sh_h1p[0][10 * lane];
                const float* p1 = &sh_h1p[1][10 * lane];
                #pragma unroll
                for (int j = 0; j < 5; ++j) {
                    a0[j] = *(const float2*)(p0 + 2 * j);
                    a1[j] = *(const float2*)(p1 + 2 * j);
                }
                #pragma unroll
                for (int rr = 0; rr < 8; ++rr) {
                    int jrow = rank * JROWS_PER + warp * 8 + rr;
                    const float* w = Wj1 + jrow * ZDIM + ENC + 10 * lane;
                    float s0 = acc[rr][0], s1 = acc[rr][1];
                    #pragma unroll
                    for (int j = 0; j < 5; ++j) {
                        float2 wv = *(const float2*)(w + 2 * j);
                        s0 = fmaf(wv.x, a0[j].x, s0); s0 = fmaf(wv.y, a0[j].y, s0);
                        s1 = fmaf(wv.x, a1[j].x, s1); s1 = fmaf(wv.y, a1[j].y, s1);
                    }
                    acc[rr][0] = s0; acc[rr][1] = s1;
                }
            }
            #pragma unroll
            for (int rr = 0; rr < 8; ++rr) {
                int jrow = rank * JROWS_PER + warp * 8 + rr;
                float r0 = wredsum(acc[rr][0]);
                float r1 = wredsum(acc[rr][1]);
                if (lane == 0) {
                    float bb = bj1[jrow];
                    float v0 = r0 + bb; v0 = v0 > 0.f ? v0 : 0.f;
                    float v1 = r1 + bb; v1 = v1 > 0.f ? v1 : 0.f;
                    uint32_t ad0 = s2u(&sh_hid[0][jrow]);
                    uint32_t ad1 = s2u(&sh_hid[1][jrow]);
                    #pragma unroll
                    for (int rk = 0; rk < CSIZE; ++rk) {
                        st_peer(ad0, rk, v0);
                        st_peer(ad1, rk, v1);
                    }
                }
            }
        }
        CLUSTER_SYNC();   // S3: full hid assembled everywhere

        // ---- P6: logits (replicated: every CTA computes all 29 x 2) ----
        if (active) {
            for (int v = warp; v < VOCAB; v += 16) {
                const float* w = Wj2 + v * JH + 16 * lane;
                float4 wv[4];
                #pragma unroll
                for (int j = 0; j < 4; ++j) wv[j] = *(const float4*)(w + 4 * j);
                float acc0 = 0.f, acc1 = 0.f;
                #pragma unroll
                for (int j = 0; j < 4; ++j) {
                    float4 h0v = *(const float4*)&sh_hid[0][16 * lane + 4 * j];
                    float4 h1v = *(const float4*)&sh_hid[1][16 * lane + 4 * j];
                    acc0 = fmaf(wv[j].x, h0v.x, acc0); acc0 = fmaf(wv[j].y, h0v.y, acc0);
                    acc0 = fmaf(wv[j].z, h0v.z, acc0); acc0 = fmaf(wv[j].w, h0v.w, acc0);
                    acc1 = fmaf(wv[j].x, h1v.x, acc1); acc1 = fmaf(wv[j].y, h1v.y, acc1);
                    acc1 = fmaf(wv[j].z, h1v.z, acc1); acc1 = fmaf(wv[j].w, h1v.w, acc1);
                }
                acc0 = wredsum(acc0);
                acc1 = wredsum(acc1);
                if (lane == 0) {
                    float bb = bj2[v];
                    sh_logit[0][v] = acc0 + bb;
                    sh_logit[1][v] = acc1 + bb;
                }
            }
        }
        __syncthreads();

        // ---- P7: argmax + control, replicated identically in every CTA ----
        if (active && tid == 0) {
            int ndone = 0;
            #pragma unroll
            for (int m = 0; m < MB; ++m) {
                float best = sh_logit[m][0]; int k = 0;
                #pragma unroll
                for (int v = 1; v < VOCAB; ++v) {
                    float lv = sh_logit[m][v];
                    if (lv > best) { best = lv; k = v; }
                }
                int ti = s_ti[m], sa = s_sa[m], lc = s_lc[m];
                bool blk = (k == BLANK);
                if (blk) ti += 1;
                bool done = (ti >= s_olen[m]);
                if (blk) sa = 0;
                bool nb = !(done || blk);
                if (nb) {
                    lc += 1;
                    if (lc <= NSTEPS - 1) sh_lt[m][lc] += (k + 1);  // JAX scatter: OOB dropped
                    sa += 1;
                }
                {
                    int pos = lc; if (pos > NSTEPS - 1) pos = NSTEPS - 1;
                    s_last[m] = sh_lt[m][pos];                       // JAX gather: clamp
                }
                if (sa >= MAXSYM) { ti += 1; sa = 0; }
                s_ti[m] = ti; s_sa[m] = sa; s_lc[m] = lc; s_nb[m] = nb ? 1 : 0;
                if (ti >= s_olen[m]) ndone += 1;   // done is permanent (ti monotone)
            }
            // When every row of this cluster is done, lt/lc are frozen forever
            // (not_blank false on all future steps) -> remaining steps can skip
            // all compute. Decision derives from state replicated identically in
            // every CTA, so all CTAs flip the flag on the same step.
            if (ndone == MB) s_alldone = 1;
        }
        __syncthreads();

        // ---- P8: conditional state commit (h full, c local slice) ----
        if (active) {
            for (int i = tid; i < MB * PRED; i += NTHREADS) {
                int m = i / PRED, j = i - m * PRED;
                if (s_nb[m]) { sh_h0[m][j] = sh_h0p[m][j]; sh_h1[m][j] = sh_h1p[m][j]; }
            }
            if (tid < MB * UNITS_PER) {
                int m  = tid / UNITS_PER, lu = tid - m * UNITS_PER;
                int gu = rank * UNITS_PER + lu;
                if (s_nb[m]) { sh_c0[m][gu] = sh_c0p[m][gu]; sh_c1[m][gu] = sh_c1p[m][gu]; }
            }
        }
        CLUSTER_SYNC();   // S4: protects h0p/h1p against next step's peer writes
    }

    // ---- output (rank 0 of each cluster): lt as float32, then lc ----
    if (rank == 0) {
        for (int m = 0; m < MB; ++m) {
            for (int i = tid; i < NSTEPS; i += NTHREADS)
                d_out[(bbase + m) * NSTEPS + i] = (float)sh_lt[m][i];
        }
        if (tid == 0 && write_lc) {
            d_out[BATCH * NSTEPS + bbase + 0] = (float)s_lc[0];
            d_out[BATCH * NSTEPS + bbase + 1] = (float)s_lc[1];
        }
    }
}

extern "C" void kernel_launch(void* const* d_in, const int* in_sizes, int n_in,
                              void* d_out, int out_size) {
    const float* x        = (const float*)d_in[0];
    const int*   out_lens = (const int*)  d_in[1];
    const float* emb      = (const float*)d_in[2];
    const float* Wi0      = (const float*)d_in[3];
    const float* Wh0      = (const float*)d_in[4];
    const float* b0       = (const float*)d_in[5];
    const float* Wi1      = (const float*)d_in[6];
    const float* Wh1      = (const float*)d_in[7];
    const float* b1       = (const float*)d_in[8];
    const float* Wj1      = (const float*)d_in[9];
    const float* bj1      = (const float*)d_in[10];
    const float* Wj2      = (const float*)d_in[11];
    const float* bj2      = (const float*)d_in[12];

    int write_lc = (out_size >= BATCH * NSTEPS + BATCH) ? 1 : 0;

    rnnt_greedy_kernel<<<(BATCH / MB) * CSIZE, NTHREADS>>>(
        x, out_lens, emb,
        Wi0, Wh0, b0, Wi1, Wh1, b1,
        Wj1, bj1, Wj2, bj2,
        (float*)d_out, write_lc);
}

// round 10
// speedup vs baseline: 1.7240x; 1.1926x over previous
#include <cuda_runtime.h>
#include <math.h>
#include <stdint.h>

#define ENC 1024
#define PRED 320
#define JH 512
#define VOCAB 29
#define BLANK 28
#define MAXSYM 6
#define BATCH 32
#define TLEN 48
#define NSTEPS 288
#define ZDIM 1344
#define CSIZE 4
#define MB 2
#define NTHREADS 512
#define UNITS_PER 80            // PRED / CSIZE
#define JROWS_PER 128           // JH / CSIZE

// Transposed weight scratch (one-time fill per launch; ~9.3 MB)
__device__ float d_WiT0[PRED * 4 * PRED];   // [320 cols][1280 rows]
__device__ float d_WhT0[PRED * 4 * PRED];
__device__ float d_WiT1[PRED * 4 * PRED];
__device__ float d_WhT1[PRED * 4 * PRED];
__device__ float d_Wj1T[ZDIM * JH];         // [1344 cols][512 rows]

#define CLUSTER_SYNC() do { \
    asm volatile("barrier.cluster.arrive.aligned;" ::: "memory"); \
    asm volatile("barrier.cluster.wait.aligned;"   ::: "memory"); \
} while (0)

__device__ __forceinline__ float sigf(float v) { return 1.0f / (1.0f + expf(-v)); }

__device__ __forceinline__ float wredsum(float v) {
    #pragma unroll
    for (int o = 16; o > 0; o >>= 1) v += __shfl_down_sync(0xffffffffu, v, o);
    return v;
}

__device__ __forceinline__ uint32_t s2u(const void* p) {
    return (uint32_t)__cvta_generic_to_shared((void*)p);
}

__device__ __forceinline__ void st_peer(uint32_t addr, int rank, float v) {
    uint32_t pa;
    asm volatile("mapa.shared::cluster.u32 %0, %1, %2;" : "=r"(pa) : "r"(addr), "r"(rank));
    asm volatile("st.shared::cluster.f32 [%0], %1;" :: "r"(pa), "f"(v));
}

// ---------------- tiled transpose: out[c][r] = in[r][c]; R,C multiples of 32 ----------------
__global__ void transpose_kernel(const float* __restrict__ in, int R, int C, int which) {
    float* out = (which == 0) ? d_WiT0 : (which == 1) ? d_WhT0 :
                 (which == 2) ? d_WiT1 : (which == 3) ? d_WhT1 : d_Wj1T;
    __shared__ float tile[32][33];
    int tilesC = C >> 5, tilesR = R >> 5;
    int ntiles = tilesC * tilesR;
    for (int t = blockIdx.x; t < ntiles; t += gridDim.x) {
        int tc = t % tilesC, tr = t / tilesC;
        int c0 = tc << 5, r0 = tr << 5;
        __syncthreads();
        #pragma unroll
        for (int j = 0; j < 32; j += 8)
            tile[threadIdx.y + j][threadIdx.x] = in[(size_t)(r0 + threadIdx.y + j) * C + c0 + threadIdx.x];
        __syncthreads();
        #pragma unroll
        for (int j = 0; j < 32; j += 8)
            out[(size_t)(c0 + threadIdx.y + j) * R + r0 + threadIdx.x] = tile[threadIdx.x][threadIdx.y + j];
    }
}

// ---------------- transposed gate GEMV ----------------
// Local rows: 320 (4 gates x 80 units for this rank). Cols: 640 = [in0(320) | in1(320)].
// Threads 0..319: split = tid/80 (cols 160*split..+159), rg = tid%80 (rows 4rg..4rg+3, float4).
// Splits 0,1 read WiT (input part), splits 2,3 read WhT (hidden part).
// Partials in scratch[ (split*2+m)*320 + lrow ]; deterministic 4-way reduce adds bias.
__device__ __forceinline__ void gemv_gates_T(
    const float* __restrict__ WiT, const float* __restrict__ WhT,
    const float* __restrict__ bias,
    const float (*in)[2 * PRED],       // [MB][640]
    float (*gout)[PRED],               // [MB][320] local gate pre-activations
    float* scratch, int rank, int tid)
{
    if (tid < 320) {
        int split = tid / 80;
        int rg    = tid - split * 80;
        int g     = rg / 20;           // gate index 0..3 (rows 4rg..4rg+3 stay in one gate)
        int rowb  = 4 * rg;            // local row base
        const float* WT = (split < 2) ? WiT : WhT;
        int cb = (split & 1) * 160;    // col base within the 320-wide matrix
        // global weight row base = g*320 + rank*80 + (rowb - 80*g) = 240*g + 80*rank + rowb
        const float* w0 = WT + (cb * 1280) + 240 * g + rank * 80 + rowb;
        const float* a0 = &in[0][split * 160];
        const float* a1 = &in[1][split * 160];
        float acc[4][2] = {{0.f,0.f},{0.f,0.f},{0.f,0.f},{0.f,0.f}};
        #pragma unroll 4
        for (int cc = 0; cc < 160; ++cc) {
            float4 w = *(const float4*)(w0 + cc * 1280);
            float x0 = a0[cc], x1 = a1[cc];
            acc[0][0] = fmaf(w.x, x0, acc[0][0]); acc[0][1] = fmaf(w.x, x1, acc[0][1]);
            acc[1][0] = fmaf(w.y, x0, acc[1][0]); acc[1][1] = fmaf(w.y, x1, acc[1][1]);
            acc[2][0] = fmaf(w.z, x0, acc[2][0]); acc[2][1] = fmaf(w.z, x1, acc[2][1]);
            acc[3][0] = fmaf(w.w, x0, acc[3][0]); acc[3][1] = fmaf(w.w, x1, acc[3][1]);
        }
        #pragma unroll
        for (int i = 0; i < 4; ++i) {
            int lrow = rowb + i;
            scratch[(split * 2 + 0) * 320 + lrow] = acc[i][0];
            scratch[(split * 2 + 1) * 320 + lrow] = acc[i][1];
        }
    }
    __syncthreads();
    for (int o = tid; o < 640; o += NTHREADS) {
        int m = o / 320, r = o - m * 320;
        float v = scratch[(0 * 2 + m) * 320 + r] + scratch[(1 * 2 + m) * 320 + r]
                + scratch[(2 * 2 + m) * 320 + r] + scratch[(3 * 2 + m) * 320 + r];
        int g = r / 80, lu = r - g * 80;
        gout[m][r] = v + bias[g * PRED + rank * UNITS_PER + lu];
    }
    // caller syncs before consuming gout
}

// ---------------- transposed joint GEMV ----------------
// Local rows: 128 (rank slice of 512). Cols: 1344. Threads 0..255: split=tid>>5 (168 cols),
// rg=tid&31 (rows 4rg..+3). Partials scratch[(split*2+m)*128 + lrow]; 8-way reduce + relu + bcast.
__device__ __forceinline__ void gemv_joint_T(
    const float* __restrict__ WT, const float* __restrict__ bias,
    const float (*zin)[ZDIM],          // [MB][1344]
    float (*hid)[JH],                  // [MB][512], assembled cluster-wide
    float* scratch, int rank, int tid)
{
    if (tid < 256) {
        int split = tid >> 5;
        int rg    = tid & 31;
        int rowb  = 4 * rg;
        const float* w0 = WT + (split * 168) * 512 + rank * JROWS_PER + rowb;
        const float* a0 = &zin[0][split * 168];
        const float* a1 = &zin[1][split * 168];
        float acc[4][2] = {{0.f,0.f},{0.f,0.f},{0.f,0.f},{0.f,0.f}};
        #pragma unroll 4
        for (int cc = 0; cc < 168; ++cc) {
            float4 w = *(const float4*)(w0 + cc * 512);
            float x0 = a0[cc], x1 = a1[cc];
            acc[0][0] = fmaf(w.x, x0, acc[0][0]); acc[0][1] = fmaf(w.x, x1, acc[0][1]);
            acc[1][0] = fmaf(w.y, x0, acc[1][0]); acc[1][1] = fmaf(w.y, x1, acc[1][1]);
            acc[2][0] = fmaf(w.z, x0, acc[2][0]); acc[2][1] = fmaf(w.z, x1, acc[2][1]);
            acc[3][0] = fmaf(w.w, x0, acc[3][0]); acc[3][1] = fmaf(w.w, x1, acc[3][1]);
        }
        #pragma unroll
        for (int i = 0; i < 4; ++i) {
            int lrow = rowb + i;
            scratch[(split * 2 + 0) * 128 + lrow] = acc[i][0];
            scratch[(split * 2 + 1) * 128 + lrow] = acc[i][1];
        }
    }
    __syncthreads();
    if (tid < 256) {
        int m = tid >> 7, lr = tid & 127;
        float v = 0.f;
        #pragma unroll
        for (int s = 0; s < 8; ++s) v += scratch[(s * 2 + m) * 128 + lr];
        v += bias[rank * JROWS_PER + lr];
        v = v > 0.f ? v : 0.f;
        uint32_t ad = s2u(&hid[m][rank * JROWS_PER + lr]);
        #pragma unroll
        for (int rk = 0; rk < CSIZE; ++rk) st_peer(ad, rk, v);
    }
    // caller cluster-syncs
}

__global__ __launch_bounds__(NTHREADS, 1) __cluster_dims__(CSIZE, 1, 1)
void rnnt_greedy_kernel(const float* __restrict__ x,
                        const int*   __restrict__ out_lens,
                        const float* __restrict__ emb,
                        const float* __restrict__ b0, const float* __restrict__ b1,
                        const float* __restrict__ bj1,
                        const float* __restrict__ Wj2, const float* __restrict__ bj2,
                        float* __restrict__ d_out, int write_lc)
{
    const int tid  = threadIdx.x;
    const int lane = tid & 31;
    const int warp = tid >> 5;

    uint32_t rank;
    asm("mov.u32 %0, %%cluster_ctarank;" : "=r"(rank));
    const int cid   = blockIdx.x / CSIZE;
    const int bbase = cid * MB;

    // [0:320]=e, [320:640]=h0(state)
    __shared__ __align__(16) float L0in[MB][2 * PRED];
    // [0:320]=h0p, [320:640]=h1(state)
    __shared__ __align__(16) float L1in[MB][2 * PRED];
    // [0:1024]=f, [1024:1344]=h1p
    __shared__ __align__(16) float zj[MB][ZDIM];
    __shared__ __align__(16) float c0s[MB][UNITS_PER], c1s[MB][UNITS_PER];
    __shared__ __align__(16) float c0p[MB][UNITS_PER], c1p[MB][UNITS_PER];
    __shared__ __align__(16) float sh_g[MB][PRED];
    __shared__ __align__(16) float scratch[2560];   // 10 KB: gates 4*2*320; joint 8*2*128
    __shared__ __align__(16) float sh_hid[MB][JH];
    __shared__ __align__(16) float sh_logit[MB][32];
    __shared__ int sh_lt[MB][NSTEPS];
    __shared__ int s_last[MB], s_lc[MB], s_ti[MB], s_sa[MB], s_nb[MB], s_olen[MB];
    __shared__ int s_alldone;

    // ---- init ----
    for (int i = tid; i < MB * PRED; i += NTHREADS) {
        int m = i / PRED, j = i - m * PRED;
        L0in[m][PRED + j] = 0.f;   // h0 = 0
        L1in[m][PRED + j] = 0.f;   // h1 = 0
    }
    for (int i = tid; i < MB * UNITS_PER; i += NTHREADS) {
        int m = i / UNITS_PER, j = i - m * UNITS_PER;
        c0s[m][j] = 0.f; c1s[m][j] = 0.f;
    }
    for (int i = tid; i < MB * NSTEPS; i += NTHREADS) {
        int m = i / NSTEPS, j = i - m * NSTEPS;
        sh_lt[m][j] = -1;
    }
    if (tid == 0) {
        #pragma unroll
        for (int m = 0; m < MB; ++m) {
            s_last[m] = -1; s_lc[m] = 0; s_ti[m] = 0; s_sa[m] = 0; s_nb[m] = 0;
            s_olen[m] = out_lens[bbase + m];
        }
        s_alldone = 0;
    }
    __syncthreads();
    CLUSTER_SYNC();

    for (int step = 0; step < NSTEPS; ++step) {
        const bool active = (s_alldone == 0);   // uniform across cluster

        // ---- P0: encoder frame -> zj[.][0:1024], embedding -> L0in[.][0:320] ----
        if (active) {
            for (int i = tid; i < MB * ENC; i += NTHREADS) {
                int m = i >> 10, col = i & (ENC - 1);
                int fi = s_ti[m]; if (fi > TLEN - 1) fi = TLEN - 1;
                zj[m][col] = x[((bbase + m) * TLEN + fi) * ENC + col];
            }
            for (int i = tid; i < MB * PRED; i += NTHREADS) {
                int m = i / PRED, col = i - m * PRED;
                int lab = s_last[m];
                int labc = lab > (VOCAB - 2) ? (VOCAB - 2) : lab;
                L0in[m][col] = (lab >= 0) ? emb[labc * PRED + col] : 0.0f;
            }
        }
        __syncthreads();

        // ---- P1: layer-0 gates (transposed GEMV; internal sync) ----
        if (active)
            gemv_gates_T(d_WiT0, d_WhT0, b0, L0in, sh_g, scratch, (int)rank, tid);
        __syncthreads();

        // ---- P2: LSTM0 nonlinearity; broadcast h0p slice ----
        if (active && tid < MB * UNITS_PER) {
            int m = tid / UNITS_PER, lu = tid - m * UNITS_PER;
            float gi = sh_g[m][lu],               gf = sh_g[m][UNITS_PER + lu];
            float gg = sh_g[m][2 * UNITS_PER + lu], go = sh_g[m][3 * UNITS_PER + lu];
            float c  = sigf(gf) * c0s[m][lu] + sigf(gi) * tanhf(gg);
            c0p[m][lu] = c;
            float h  = sigf(go) * tanhf(c);
            uint32_t a = s2u(&L1in[m][rank * UNITS_PER + lu]);
            #pragma unroll
            for (int rk = 0; rk < CSIZE; ++rk) st_peer(a, rk, h);
        }
        CLUSTER_SYNC();   // S1: full h0p in L1in[.][0:320] everywhere

        // ---- P3: layer-1 gates ----
        if (active)
            gemv_gates_T(d_WiT1, d_WhT1, b1, L1in, sh_g, scratch, (int)rank, tid);
        __syncthreads();

        // ---- P4: LSTM1 nonlinearity; broadcast h1p slice ----
        if (active && tid < MB * UNITS_PER) {
            int m = tid / UNITS_PER, lu = tid - m * UNITS_PER;
            float gi = sh_g[m][lu],               gf = sh_g[m][UNITS_PER + lu];
            float gg = sh_g[m][2 * UNITS_PER + lu], go = sh_g[m][3 * UNITS_PER + lu];
            float c  = sigf(gf) * c1s[m][lu] + sigf(gi) * tanhf(gg);
            c1p[m][lu] = c;
            float h  = sigf(go) * tanhf(c);
            uint32_t a = s2u(&zj[m][ENC + rank * UNITS_PER + lu]);
            #pragma unroll
            for (int rk = 0; rk < CSIZE; ++rk) st_peer(a, rk, h);
        }
        CLUSTER_SYNC();   // S2: full [f|h1p] in zj everywhere

        // ---- P5: joint hidden (transposed GEMV; internal sync; broadcasts hid) ----
        if (active)
            gemv_joint_T(d_Wj1T, bj1, zj, sh_hid, scratch, (int)rank, tid);
        CLUSTER_SYNC();   // S3: full hid everywhere

        // ---- P6: logits (replicated; warp per vocab row) ----
        if (active) {
            for (int v = warp; v < VOCAB; v += 16) {
                const float* w = Wj2 + v * JH + 16 * lane;
                float4 wv[4];
                #pragma unroll
                for (int j = 0; j < 4; ++j) wv[j] = *(const float4*)(w + 4 * j);
                float acc0 = 0.f, acc1 = 0.f;
                #pragma unroll
                for (int j = 0; j < 4; ++j) {
                    float4 h0v = *(const float4*)&sh_hid[0][16 * lane + 4 * j];
                    float4 h1v = *(const float4*)&sh_hid[1][16 * lane + 4 * j];
                    acc0 = fmaf(wv[j].x, h0v.x, acc0); acc0 = fmaf(wv[j].y, h0v.y, acc0);
                    acc0 = fmaf(wv[j].z, h0v.z, acc0); acc0 = fmaf(wv[j].w, h0v.w, acc0);
                    acc1 = fmaf(wv[j].x, h1v.x, acc1); acc1 = fmaf(wv[j].y, h1v.y, acc1);
                    acc1 = fmaf(wv[j].z, h1v.z, acc1); acc1 = fmaf(wv[j].w, h1v.w, acc1);
                }
                acc0 = wredsum(acc0);
                acc1 = wredsum(acc1);
                if (lane == 0) {
                    float bb = bj2[v];
                    sh_logit[0][v] = acc0 + bb;
                    sh_logit[1][v] = acc1 + bb;
                }
            }
        }
        __syncthreads();

        // ---- P7: argmax + control (replicated; identical in every CTA) ----
        if (active && tid == 0) {
            int ndone = 0;
            #pragma unroll
            for (int m = 0; m < MB; ++m) {
                float best = sh_logit[m][0]; int k = 0;
                #pragma unroll
                for (int v = 1; v < VOCAB; ++v) {
                    float lv = sh_logit[m][v];
                    if (lv > best) { best = lv; k = v; }
                }
                int ti = s_ti[m], sa = s_sa[m], lc = s_lc[m];
                bool blk = (k == BLANK);
                if (blk) ti += 1;
                bool done = (ti >= s_olen[m]);
                if (blk) sa = 0;
                bool nb = !(done || blk);
                if (nb) {
                    lc += 1;
                    if (lc <= NSTEPS - 1) sh_lt[m][lc] += (k + 1);  // JAX scatter: OOB dropped
                    sa += 1;
                }
                {
                    int pos = lc; if (pos > NSTEPS - 1) pos = NSTEPS - 1;
                    s_last[m] = sh_lt[m][pos];                       // JAX gather: clamp
                }
                if (sa >= MAXSYM) { ti += 1; sa = 0; }
                s_ti[m] = ti; s_sa[m] = sa; s_lc[m] = lc; s_nb[m] = nb ? 1 : 0;
                if (ti >= s_olen[m]) ndone += 1;
            }
            if (ndone == MB) s_alldone = 1;   // outputs frozen from here on
        }
        __syncthreads();

        // ---- P8: conditional state commit ----
        if (active) {
            for (int i = tid; i < MB * PRED; i += NTHREADS) {
                int m = i / PRED, u = i - m * PRED;
                if (s_nb[m]) {
                    L0in[m][PRED + u] = L1in[m][u];        // h0 <- h0p
                    L1in[m][PRED + u] = zj[m][ENC + u];    // h1 <- h1p
                }
            }
            if (tid < MB * UNITS_PER) {
                int m = tid / UNITS_PER, lu = tid - m * UNITS_PER;
                if (s_nb[m]) { c0s[m][lu] = c0p[m][lu]; c1s[m][lu] = c1p[m][lu]; }
            }
        }
        CLUSTER_SYNC();   // S4: protects h0p/h1p regions against next step's peer writes
    }

    // ---- output (rank 0): lt as float32, then lc ----
    if (rank == 0) {
        for (int m = 0; m < MB; ++m) {
            for (int i = tid; i < NSTEPS; i += NTHREADS)
                d_out[(bbase + m) * NSTEPS + i] = (float)sh_lt[m][i];
        }
        if (tid == 0 && write_lc) {
            d_out[BATCH * NSTEPS + bbase + 0] = (float)s_lc[0];
            d_out[BATCH * NSTEPS + bbase + 1] = (float)s_lc[1];
        }
    }
}

extern "C" void kernel_launch(void* const* d_in, const int* in_sizes, int n_in,
                              void* d_out, int out_size) {
    const float* x        = (const float*)d_in[0];
    const int*   out_lens = (const int*)  d_in[1];
    const float* emb      = (const float*)d_in[2];
    const float* Wi0      = (const float*)d_in[3];
    const float* Wh0      = (const float*)d_in[4];
    const float* b0       = (const float*)d_in[5];
    const float* Wi1      = (const float*)d_in[6];
    const float* Wh1      = (const float*)d_in[7];
    const float* b1       = (const float*)d_in[8];
    const float* Wj1      = (const float*)d_in[9];
    const float* bj1      = (const float*)d_in[10];
    const float* Wj2      = (const float*)d_in[11];
    const float* bj2      = (const float*)d_in[12];

    int write_lc = (out_size >= BATCH * NSTEPS + BATCH) ? 1 : 0;

    dim3 tb(32, 8);
    transpose_kernel<<<512, tb>>>(Wi0, 4 * PRED, PRED, 0);
    transpose_kernel<<<512, tb>>>(Wh0, 4 * PRED, PRED, 1);
    transpose_kernel<<<512, tb>>>(Wi1, 4 * PRED, PRED, 2);
    transpose_kernel<<<512, tb>>>(Wh1, 4 * PRED, PRED, 3);
    transpose_kernel<<<512, tb>>>(Wj1, JH, ZDIM, 4);

    rnnt_greedy_kernel<<<(BATCH / MB) * CSIZE, NTHREADS>>>(
        x, out_lens, emb, b0, b1, bj1, Wj2, bj2,
        (float*)d_out, write_lc);
}

// round 11
// speedup vs baseline: 2.3380x; 1.3562x over previous
#include <cuda_runtime.h>
#include <math.h>
#include <stdint.h>

#define ENC 1024
#define PRED 320
#define JH 512
#define VOCAB 29
#define BLANK 28
#define MAXSYM 6
#define BATCH 32
#define TLEN 48
#define NSTEPS 288
#define ZDIM 1344
#define CSIZE 4
#define MB 2
#define NTHREADS 640
#define UNITS_PER 80            // PRED / CSIZE
#define JROWS_PER 128           // JH / CSIZE

// Transposed weight scratch (one-time fill per launch; ~9.3 MB)
__device__ float d_WiT0[PRED * 4 * PRED];   // [320 cols][1280 rows]
__device__ float d_WhT0[PRED * 4 * PRED];
__device__ float d_WiT1[PRED * 4 * PRED];
__device__ float d_WhT1[PRED * 4 * PRED];
__device__ float d_Wj1T[ZDIM * JH];         // [1344 cols][512 rows]

#define CLUSTER_SYNC() do { \
    asm volatile("barrier.cluster.arrive.aligned;" ::: "memory"); \
    asm volatile("barrier.cluster.wait.aligned;"   ::: "memory"); \
} while (0)

__device__ __forceinline__ float sigf(float v) { return 1.0f / (1.0f + expf(-v)); }

__device__ __forceinline__ float wredsum(float v) {
    #pragma unroll
    for (int o = 16; o > 0; o >>= 1) v += __shfl_down_sync(0xffffffffu, v, o);
    return v;
}

__device__ __forceinline__ uint32_t s2u(const void* p) {
    return (uint32_t)__cvta_generic_to_shared((void*)p);
}

__device__ __forceinline__ void st_peer(uint32_t addr, int rank, float v) {
    uint32_t pa;
    asm volatile("mapa.shared::cluster.u32 %0, %1, %2;" : "=r"(pa) : "r"(addr), "r"(rank));
    asm volatile("st.shared::cluster.f32 [%0], %1;" :: "r"(pa), "f"(v));
}

// ---------------- tiled transpose: out[c][r] = in[r][c]; R,C multiples of 32 ----------------
__global__ void transpose_kernel(const float* __restrict__ in, int R, int C, int which) {
    float* out = (which == 0) ? d_WiT0 : (which == 1) ? d_WhT0 :
                 (which == 2) ? d_WiT1 : (which == 3) ? d_WhT1 : d_Wj1T;
    __shared__ float tile[32][33];
    int tilesC = C >> 5, tilesR = R >> 5;
    int ntiles = tilesC * tilesR;
    for (int t = blockIdx.x; t < ntiles; t += gridDim.x) {
        int tc = t % tilesC, tr = t / tilesC;
        int c0 = tc << 5, r0 = tr << 5;
        __syncthreads();
        #pragma unroll
        for (int j = 0; j < 32; j += 8)
            tile[threadIdx.y + j][threadIdx.x] = in[(size_t)(r0 + threadIdx.y + j) * C + c0 + threadIdx.x];
        __syncthreads();
        #pragma unroll
        for (int j = 0; j < 32; j += 8)
            out[(size_t)(c0 + threadIdx.y + j) * R + r0 + threadIdx.x] = tile[threadIdx.x][threadIdx.y + j];
    }
}

// ---------------- transposed gate GEMV (640 active threads) ----------------
// Local rows: 320 (4 gates x 80 units for this rank). Cols: 640 = [in0(320) | in1(320)].
// Threads 0..639: split = tid/160 (col range 160*split..+159 of the concat),
// rg = tid%160 -> local rows 2rg, 2rg+1 (float2 weight load).
// Splits 0,1 read WiT (input part), splits 2,3 read WhT.
// Same column partition & per-split accumulation order as the R10 kernel
// -> bit-identical results; only the thread mapping changed (2-row groups).
__device__ __forceinline__ void gemv_gates_T(
    const float* __restrict__ WiT, const float* __restrict__ WhT,
    const float* __restrict__ bias,
    const float (*in)[2 * PRED],       // [MB][640]
    float (*gout)[PRED],               // [MB][320] local gate pre-activations
    float* scratch, int rank, int tid)
{
    {
        int split = tid / 160;
        int rg    = tid - split * 160;
        int rowb  = 2 * rg;            // local row base (0..318)
        int g     = rg / 40;           // gate index 0..3 (= rowb/80)
        const float* WT = (split < 2) ? WiT : WhT;
        int cb = (split & 1) * 160;    // col base within the 320-wide matrix
        // global weight row base = 240*g + 80*rank + rowb (see R10 derivation)
        const float* w0 = WT + (cb * 1280) + 240 * g + rank * 80 + rowb;
        const float* a0 = &in[0][split * 160];
        const float* a1 = &in[1][split * 160];
        float acc[2][2] = {{0.f,0.f},{0.f,0.f}};
        #pragma unroll 8
        for (int cc = 0; cc < 160; ++cc) {
            float2 w = *(const float2*)(w0 + cc * 1280);
            float x0 = a0[cc], x1 = a1[cc];
            acc[0][0] = fmaf(w.x, x0, acc[0][0]); acc[0][1] = fmaf(w.x, x1, acc[0][1]);
            acc[1][0] = fmaf(w.y, x0, acc[1][0]); acc[1][1] = fmaf(w.y, x1, acc[1][1]);
        }
        #pragma unroll
        for (int i = 0; i < 2; ++i) {
            int lrow = rowb + i;
            scratch[(split * 2 + 0) * 320 + lrow] = acc[i][0];
            scratch[(split * 2 + 1) * 320 + lrow] = acc[i][1];
        }
    }
    __syncthreads();
    for (int o = tid; o < 640; o += NTHREADS) {
        int m = o / 320, r = o - m * 320;
        float v = scratch[(0 * 2 + m) * 320 + r] + scratch[(1 * 2 + m) * 320 + r]
                + scratch[(2 * 2 + m) * 320 + r] + scratch[(3 * 2 + m) * 320 + r];
        int g = r / 80, lu = r - g * 80;
        gout[m][r] = v + bias[g * PRED + rank * UNITS_PER + lu];
    }
    // caller syncs before consuming gout
}

// ---------------- transposed joint GEMV (512 active threads) ----------------
// Local rows: 128 (rank slice of 512). Cols: 1344 = 8 splits x 168.
// Threads 0..511: split = tid>>6 (168 cols), rg = tid&63 -> rows 2rg, 2rg+1 (float2).
// Same 8x168 col partition & order as R10 -> bit-identical.
__device__ __forceinline__ void gemv_joint_T(
    const float* __restrict__ WT, const float* __restrict__ bias,
    const float (*zin)[ZDIM],          // [MB][1344]
    float (*hid)[JH],                  // [MB][512], assembled cluster-wide
    float* scratch, int rank, int tid)
{
    if (tid < 512) {
        int split = tid >> 6;
        int rg    = tid & 63;
        int rowb  = 2 * rg;
        const float* w0 = WT + (split * 168) * 512 + rank * JROWS_PER + rowb;
        const float* a0 = &zin[0][split * 168];
        const float* a1 = &zin[1][split * 168];
        float acc[2][2] = {{0.f,0.f},{0.f,0.f}};
        #pragma unroll 8
        for (int cc = 0; cc < 168; ++cc) {
            float2 w = *(const float2*)(w0 + cc * 512);
            float x0 = a0[cc], x1 = a1[cc];
            acc[0][0] = fmaf(w.x, x0, acc[0][0]); acc[0][1] = fmaf(w.x, x1, acc[0][1]);
            acc[1][0] = fmaf(w.y, x0, acc[1][0]); acc[1][1] = fmaf(w.y, x1, acc[1][1]);
        }
        #pragma unroll
        for (int i = 0; i < 2; ++i) {
            int lrow = rowb + i;
            scratch[(split * 2 + 0) * 128 + lrow] = acc[i][0];
            scratch[(split * 2 + 1) * 128 + lrow] = acc[i][1];
        }
    }
    __syncthreads();
    if (tid < 256) {
        int m = tid >> 7, lr = tid & 127;
        float v = 0.f;
        #pragma unroll
        for (int s = 0; s < 8; ++s) v += scratch[(s * 2 + m) * 128 + lr];
        v += bias[rank * JROWS_PER + lr];
        v = v > 0.f ? v : 0.f;
        uint32_t ad = s2u(&hid[m][rank * JROWS_PER + lr]);
        #pragma unroll
        for (int rk = 0; rk < CSIZE; ++rk) st_peer(ad, rk, v);
    }
    // caller cluster-syncs
}

__global__ __launch_bounds__(NTHREADS, 1) __cluster_dims__(CSIZE, 1, 1)
void rnnt_greedy_kernel(const float* __restrict__ x,
                        const int*   __restrict__ out_lens,
                        const float* __restrict__ emb,
                        const float* __restrict__ b0, const float* __restrict__ b1,
                        const float* __restrict__ bj1,
                        const float* __restrict__ Wj2, const float* __restrict__ bj2,
                        float* __restrict__ d_out, int write_lc)
{
    const int tid  = threadIdx.x;
    const int lane = tid & 31;
    const int warp = tid >> 5;

    uint32_t rank;
    asm("mov.u32 %0, %%cluster_ctarank;" : "=r"(rank));
    const int cid   = blockIdx.x / CSIZE;
    const int bbase = cid * MB;

    // [0:320]=e, [320:640]=h0(state)
    __shared__ __align__(16) float L0in[MB][2 * PRED];
    // [0:320]=h0p, [320:640]=h1(state)
    __shared__ __align__(16) float L1in[MB][2 * PRED];
    // [0:1024]=f, [1024:1344]=h1p
    __shared__ __align__(16) float zj[MB][ZDIM];
    __shared__ __align__(16) float c0s[MB][UNITS_PER], c1s[MB][UNITS_PER];
    __shared__ __align__(16) float c0p[MB][UNITS_PER], c1p[MB][UNITS_PER];
    __shared__ __align__(16) float sh_g[MB][PRED];
    __shared__ __align__(16) float scratch[2560];   // 10 KB: gates 4*2*320; joint 8*2*128
    __shared__ __align__(16) float sh_hid[MB][JH];
    __shared__ __align__(16) float sh_logit[MB][32];
    __shared__ int sh_lt[MB][NSTEPS];
    __shared__ int s_last[MB], s_lc[MB], s_ti[MB], s_sa[MB], s_nb[MB], s_olen[MB];
    __shared__ int s_alldone;

    // ---- init ----
    for (int i = tid; i < MB * PRED; i += NTHREADS) {
        int m = i / PRED, j = i - m * PRED;
        L0in[m][PRED + j] = 0.f;   // h0 = 0
        L1in[m][PRED + j] = 0.f;   // h1 = 0
    }
    for (int i = tid; i < MB * UNITS_PER; i += NTHREADS) {
        int m = i / UNITS_PER, j = i - m * UNITS_PER;
        c0s[m][j] = 0.f; c1s[m][j] = 0.f;
    }
    for (int i = tid; i < MB * NSTEPS; i += NTHREADS) {
        int m = i / NSTEPS, j = i - m * NSTEPS;
        sh_lt[m][j] = -1;
    }
    if (tid == 0) {
        #pragma unroll
        for (int m = 0; m < MB; ++m) {
            s_last[m] = -1; s_lc[m] = 0; s_ti[m] = 0; s_sa[m] = 0; s_nb[m] = 0;
            s_olen[m] = out_lens[bbase + m];
        }
        s_alldone = 0;
    }
    __syncthreads();
    CLUSTER_SYNC();

    for (int step = 0; step < NSTEPS; ++step) {
        const bool active = (s_alldone == 0);   // uniform across cluster

        // ---- P0: encoder frame -> zj[.][0:1024], embedding -> L0in[.][0:320] ----
        if (active) {
            for (int i = tid; i < MB * ENC; i += NTHREADS) {
                int m = i >> 10, col = i & (ENC - 1);
                int fi = s_ti[m]; if (fi > TLEN - 1) fi = TLEN - 1;
                zj[m][col] = x[((bbase + m) * TLEN + fi) * ENC + col];
            }
            for (int i = tid; i < MB * PRED; i += NTHREADS) {
                int m = i / PRED, col = i - m * PRED;
                int lab = s_last[m];
                int labc = lab > (VOCAB - 2) ? (VOCAB - 2) : lab;
                L0in[m][col] = (lab >= 0) ? emb[labc * PRED + col] : 0.0f;
            }
        }
        __syncthreads();

        // ---- P1: layer-0 gates (transposed GEMV; internal sync) ----
        if (active)
            gemv_gates_T(d_WiT0, d_WhT0, b0, L0in, sh_g, scratch, (int)rank, tid);
        __syncthreads();

        // ---- P2: LSTM0 nonlinearity; broadcast h0p slice ----
        if (active && tid < MB * UNITS_PER) {
            int m = tid / UNITS_PER, lu = tid - m * UNITS_PER;
            float gi = sh_g[m][lu],               gf = sh_g[m][UNITS_PER + lu];
            float gg = sh_g[m][2 * UNITS_PER + lu], go = sh_g[m][3 * UNITS_PER + lu];
            float c  = sigf(gf) * c0s[m][lu] + sigf(gi) * tanhf(gg);
            c0p[m][lu] = c;
            float h  = sigf(go) * tanhf(c);
            uint32_t a = s2u(&L1in[m][rank * UNITS_PER + lu]);
            #pragma unroll
            for (int rk = 0; rk < CSIZE; ++rk) st_peer(a, rk, h);
        }
        CLUSTER_SYNC();   // S1: full h0p in L1in[.][0:320] everywhere

        // ---- P3: layer-1 gates ----
        if (active)
            gemv_gates_T(d_WiT1, d_WhT1, b1, L1in, sh_g, scratch, (int)rank, tid);
        __syncthreads();

        // ---- P4: LSTM1 nonlinearity; broadcast h1p slice ----
        if (active && tid < MB * UNITS_PER) {
            int m = tid / UNITS_PER, lu = tid - m * UNITS_PER;
            float gi = sh_g[m][lu],               gf = sh_g[m][UNITS_PER + lu];
            float gg = sh_g[m][2 * UNITS_PER + lu], go = sh_g[m][3 * UNITS_PER + lu];
            float c  = sigf(gf) * c1s[m][lu] + sigf(gi) * tanhf(gg);
            c1p[m][lu] = c;
            float h  = sigf(go) * tanhf(c);
            uint32_t a = s2u(&zj[m][ENC + rank * UNITS_PER + lu]);
            #pragma unroll
            for (int rk = 0; rk < CSIZE; ++rk) st_peer(a, rk, h);
        }
        CLUSTER_SYNC();   // S2: full [f|h1p] in zj everywhere

        // ---- P5: joint hidden (transposed GEMV; internal sync; broadcasts hid) ----
        if (active)
            gemv_joint_T(d_Wj1T, bj1, zj, sh_hid, scratch, (int)rank, tid);
        CLUSTER_SYNC();   // S3: full hid everywhere

        // ---- P6: logits (replicated; warp per vocab row) ----
        if (active) {
            for (int v = warp; v < VOCAB; v += (NTHREADS / 32)) {
                const float* w = Wj2 + v * JH + 16 * lane;
                float4 wv[4];
                #pragma unroll
                for (int j = 0; j < 4; ++j) wv[j] = *(const float4*)(w + 4 * j);
                float acc0 = 0.f, acc1 = 0.f;
                #pragma unroll
                for (int j = 0; j < 4; ++j) {
                    float4 h0v = *(const float4*)&sh_hid[0][16 * lane + 4 * j];
                    float4 h1v = *(const float4*)&sh_hid[1][16 * lane + 4 * j];
                    acc0 = fmaf(wv[j].x, h0v.x, acc0); acc0 = fmaf(wv[j].y, h0v.y, acc0);
                    acc0 = fmaf(wv[j].z, h0v.z, acc0); acc0 = fmaf(wv[j].w, h0v.w, acc0);
                    acc1 = fmaf(wv[j].x, h1v.x, acc1); acc1 = fmaf(wv[j].y, h1v.y, acc1);
                    acc1 = fmaf(wv[j].z, h1v.z, acc1); acc1 = fmaf(wv[j].w, h1v.w, acc1);
                }
                acc0 = wredsum(acc0);
                acc1 = wredsum(acc1);
                if (lane == 0) {
                    float bb = bj2[v];
                    sh_logit[0][v] = acc0 + bb;
                    sh_logit[1][v] = acc1 + bb;
                }
            }
        }
        __syncthreads();

        // ---- P7: argmax + control (replicated; identical in every CTA) ----
        if (active && tid == 0) {
            int ndone = 0;
            #pragma unroll
            for (int m = 0; m < MB; ++m) {
                float best = sh_logit[m][0]; int k = 0;
                #pragma unroll
                for (int v = 1; v < VOCAB; ++v) {
                    float lv = sh_logit[m][v];
                    if (lv > best) { best = lv; k = v; }
                }
                int ti = s_ti[m], sa = s_sa[m], lc = s_lc[m];
                bool blk = (k == BLANK);
                if (blk) ti += 1;
                bool done = (ti >= s_olen[m]);
                if (blk) sa = 0;
                bool nb = !(done || blk);
                if (nb) {
                    lc += 1;
                    if (lc <= NSTEPS - 1) sh_lt[m][lc] += (k + 1);  // JAX scatter: OOB dropped
                    sa += 1;
                }
                {
                    int pos = lc; if (pos > NSTEPS - 1) pos = NSTEPS - 1;
                    s_last[m] = sh_lt[m][pos];                       // JAX gather: clamp
                }
                if (sa >= MAXSYM) { ti += 1; sa = 0; }
                s_ti[m] = ti; s_sa[m] = sa; s_lc[m] = lc; s_nb[m] = nb ? 1 : 0;
                if (ti >= s_olen[m]) ndone += 1;
            }
            if (ndone == MB) s_alldone = 1;   // outputs frozen from here on
        }
        __syncthreads();

        // ---- P8: conditional state commit ----
        if (active) {
            for (int i = tid; i < MB * PRED; i += NTHREADS) {
                int m = i / PRED, u = i - m * PRED;
                if (s_nb[m]) {
                    L0in[m][PRED + u] = L1in[m][u];        // h0 <- h0p
                    L1in[m][PRED + u] = zj[m][ENC + u];    // h1 <- h1p
                }
            }
            if (tid < MB * UNITS_PER) {
                int m = tid / UNITS_PER, lu = tid - m * UNITS_PER;
                if (s_nb[m]) { c0s[m][lu] = c0p[m][lu]; c1s[m][lu] = c1p[m][lu]; }
            }
        }
        CLUSTER_SYNC();   // S4: protects h0p/h1p regions against next step's peer writes
    }

    // ---- output (rank 0): lt as float32, then lc ----
    if (rank == 0) {
        for (int m = 0; m < MB; ++m) {
            for (int i = tid; i < NSTEPS; i += NTHREADS)
                d_out[(bbase + m) * NSTEPS + i] = (float)sh_lt[m][i];
        }
        if (tid == 0 && write_lc) {
            d_out[BATCH * NSTEPS + bbase + 0] = (float)s_lc[0];
            d_out[BATCH * NSTEPS + bbase + 1] = (float)s_lc[1];
        }
    }
}

extern "C" void kernel_launch(void* const* d_in, const int* in_sizes, int n_in,
                              void* d_out, int out_size) {
    const float* x        = (const float*)d_in[0];
    const int*   out_lens = (const int*)  d_in[1];
    const float* emb      = (const float*)d_in[2];
    const float* Wi0      = (const float*)d_in[3];
    const float* Wh0      = (const float*)d_in[4];
    const float* b0       = (const float*)d_in[5];
    const float* Wi1      = (const float*)d_in[6];
    const float* Wh1      = (const float*)d_in[7];
    const float* b1       = (const float*)d_in[8];
    const float* Wj1      = (const float*)d_in[9];
    const float* bj1      = (const float*)d_in[10];
    const float* Wj2      = (const float*)d_in[11];
    const float* bj2      = (const float*)d_in[12];

    int write_lc = (out_size >= BATCH * NSTEPS + BATCH) ? 1 : 0;

    dim3 tb(32, 8);
    transpose_kernel<<<512, tb>>>(Wi0, 4 * PRED, PRED, 0);
    transpose_kernel<<<512, tb>>>(Wh0, 4 * PRED, PRED, 1);
    transpose_kernel<<<512, tb>>>(Wi1, 4 * PRED, PRED, 2);
    transpose_kernel<<<512, tb>>>(Wh1, 4 * PRED, PRED, 3);
    transpose_kernel<<<512, tb>>>(Wj1, JH, ZDIM, 4);

    rnnt_greedy_kernel<<<(BATCH / MB) * CSIZE, NTHREADS>>>(
        x, out_lens, emb, b0, b1, bj1, Wj2, bj2,
        (float*)d_out, write_lc);
}

// round 12
// speedup vs baseline: 2.5030x; 1.0706x over previous
#include <cuda_runtime.h>
#include <math.h>
#include <stdint.h>

#define ENC 1024
#define PRED 320
#define JH 512
#define VOCAB 29
#define BLANK 28
#define MAXSYM 6
#define BATCH 32
#define TLEN 48
#define NSTEPS 288
#define ZDIM 1344
#define CSIZE 4
#define MB 2
#define NTHREADS 640
#define UNITS_PER 80            // PRED / CSIZE
#define JROWS_PER 128           // JH / CSIZE

// Transposed weight scratch (one-time fill per launch; ~9.3 MB)
__device__ float d_WiT0[PRED * 4 * PRED];   // [320 cols][1280 rows]
__device__ float d_WhT0[PRED * 4 * PRED];
__device__ float d_WiT1[PRED * 4 * PRED];
__device__ float d_WhT1[PRED * 4 * PRED];
__device__ float d_Wj1T[ZDIM * JH];         // [1344 cols][512 rows]

#define CLUSTER_SYNC() do { \
    asm volatile("barrier.cluster.arrive.aligned;" ::: "memory"); \
    asm volatile("barrier.cluster.wait.aligned;"   ::: "memory"); \
} while (0)

__device__ __forceinline__ float sigf(float v) { return 1.0f / (1.0f + expf(-v)); }

__device__ __forceinline__ float wredsum(float v) {
    #pragma unroll
    for (int o = 16; o > 0; o >>= 1) v += __shfl_down_sync(0xffffffffu, v, o);
    return v;
}

__device__ __forceinline__ uint32_t s2u(const void* p) {
    return (uint32_t)__cvta_generic_to_shared((void*)p);
}

__device__ __forceinline__ void st_peer(uint32_t addr, int rank, float v) {
    uint32_t pa;
    asm volatile("mapa.shared::cluster.u32 %0, %1, %2;" : "=r"(pa) : "r"(addr), "r"(rank));
    asm volatile("st.shared::cluster.f32 [%0], %1;" :: "r"(pa), "f"(v));
}

// ---------------- tiled transpose: out[c][r] = in[r][c]; R,C multiples of 32 ----------------
__global__ void transpose_kernel(const float* __restrict__ in, int R, int C, int which) {
    float* out = (which == 0) ? d_WiT0 : (which == 1) ? d_WhT0 :
                 (which == 2) ? d_WiT1 : (which == 3) ? d_WhT1 : d_Wj1T;
    __shared__ float tile[32][33];
    int tilesC = C >> 5, tilesR = R >> 5;
    int ntiles = tilesC * tilesR;
    for (int t = blockIdx.x; t < ntiles; t += gridDim.x) {
        int tc = t % tilesC, tr = t / tilesC;
        int c0 = tc << 5, r0 = tr << 5;
        __syncthreads();
        #pragma unroll
        for (int j = 0; j < 32; j += 8)
            tile[threadIdx.y + j][threadIdx.x] = in[(size_t)(r0 + threadIdx.y + j) * C + c0 + threadIdx.x];
        __syncthreads();
        #pragma unroll
        for (int j = 0; j < 32; j += 8)
            out[(size_t)(c0 + threadIdx.y + j) * R + r0 + threadIdx.x] = tile[threadIdx.x][threadIdx.y + j];
    }
}

// ---------------- dynamic shared-memory layout ----------------
struct Smem {
    float L0in[MB][2 * PRED];     // [0:320]=e, [320:640]=h0(state)
    float L1in[MB][2 * PRED];     // [0:320]=h0p, [320:640]=h1(state)
    float zj[MB][ZDIM];           // [0:1024]=f, [1024:1344]=h1p
    float c0s[MB][UNITS_PER], c1s[MB][UNITS_PER];
    float c0p[MB][UNITS_PER], c1p[MB][UNITS_PER];
    float g[MB][PRED];
    float scratch[8 * 2 * PRED];  // 20 KB; joint uses 16*2*128 = 16 KB subset
    float hid[MB][JH];
    float logit[MB][32];
    int   lt[MB][NSTEPS];
};
#define SMEM_BYTES ((int)sizeof(Smem))

// ---------------- transposed gate GEMV: 8 col-splits, float4 rows, 640 threads ----------------
// Local rows: 320 (4 gates x 80 units for this rank). Cols: 640 = [in0(320) | hid(320)].
// split = tid/80 (0..7): splits 0-3 read WiT cols 80*(split&3).. ; splits 4-7 read WhT.
// rg = tid%80 -> local rows 4rg..4rg+3 (one float4 weight load per column).
__device__ __forceinline__ void gemv_gates_T(
    const float* __restrict__ WiT, const float* __restrict__ WhT,
    const float* __restrict__ bias,
    const float (*in)[2 * PRED],       // [MB][640]
    float (*gout)[PRED],               // [MB][320] local gate pre-activations
    float* scratch, int rank, int tid)
{
    {
        int split = tid / 80;          // 0..7
        int rg    = tid - split * 80;  // 0..79
        int rowb  = 4 * rg;            // local row base 0..316
        int g     = rg / 20;           // gate index (= rowb/80)
        const float* WT = (split < 4) ? WiT : WhT;
        int cb = (split & 3) * 80;     // col base within the 320-wide matrix
        // global weight row base = 240*g + 80*rank + rowb
        const float* w0 = WT + (cb * 1280) + 240 * g + rank * 80 + rowb;
        const float* a0 = &in[0][(split < 4 ? 0 : 320) + cb];
        const float* a1 = &in[1][(split < 4 ? 0 : 320) + cb];
        float acc[4][2] = {{0.f,0.f},{0.f,0.f},{0.f,0.f},{0.f,0.f}};
        #pragma unroll 4
        for (int cc = 0; cc < 80; ++cc) {
            float4 w = *(const float4*)(w0 + cc * 1280);
            float x0 = a0[cc], x1 = a1[cc];
            acc[0][0] = fmaf(w.x, x0, acc[0][0]); acc[0][1] = fmaf(w.x, x1, acc[0][1]);
            acc[1][0] = fmaf(w.y, x0, acc[1][0]); acc[1][1] = fmaf(w.y, x1, acc[1][1]);
            acc[2][0] = fmaf(w.z, x0, acc[2][0]); acc[2][1] = fmaf(w.z, x1, acc[2][1]);
            acc[3][0] = fmaf(w.w, x0, acc[3][0]); acc[3][1] = fmaf(w.w, x1, acc[3][1]);
        }
        #pragma unroll
        for (int i = 0; i < 4; ++i) {
            int lrow = rowb + i;
            scratch[(split * 2 + 0) * 320 + lrow] = acc[i][0];
            scratch[(split * 2 + 1) * 320 + lrow] = acc[i][1];
        }
    }
    __syncthreads();
    for (int o = tid; o < 640; o += NTHREADS) {
        int m = o / 320, r = o - m * 320;
        float v = scratch[(0 * 2 + m) * 320 + r];
        #pragma unroll
        for (int s = 1; s < 8; ++s) v += scratch[(s * 2 + m) * 320 + r];
        int g = r / 80, lu = r - g * 80;
        gout[m][r] = v + bias[g * PRED + rank * UNITS_PER + lu];
    }
    // caller syncs before consuming gout
}

// ---------------- transposed joint GEMV: 16 col-splits, float4 rows, 512 threads ----------------
// Local rows: 128 (rank slice of 512). Cols: 1344 = 16 splits x 84.
// split = tid>>5 (0..15), rg = tid&31 -> rows 4rg..4rg+3 (float4).
__device__ __forceinline__ void gemv_joint_T(
    const float* __restrict__ WT, const float* __restrict__ bias,
    const float (*zin)[ZDIM],          // [MB][1344]
    float (*hid)[JH],                  // [MB][512], assembled cluster-wide
    float* scratch, int rank, int tid)
{
    if (tid < 512) {
        int split = tid >> 5;          // 0..15
        int rg    = tid & 31;
        int rowb  = 4 * rg;            // 0..124
        const float* w0 = WT + (split * 84) * 512 + rank * JROWS_PER + rowb;
        const float* a0 = &zin[0][split * 84];
        const float* a1 = &zin[1][split * 84];
        float acc[4][2] = {{0.f,0.f},{0.f,0.f},{0.f,0.f},{0.f,0.f}};
        #pragma unroll 4
        for (int cc = 0; cc < 84; ++cc) {
            float4 w = *(const float4*)(w0 + cc * 512);
            float x0 = a0[cc], x1 = a1[cc];
            acc[0][0] = fmaf(w.x, x0, acc[0][0]); acc[0][1] = fmaf(w.x, x1, acc[0][1]);
            acc[1][0] = fmaf(w.y, x0, acc[1][0]); acc[1][1] = fmaf(w.y, x1, acc[1][1]);
            acc[2][0] = fmaf(w.z, x0, acc[2][0]); acc[2][1] = fmaf(w.z, x1, acc[2][1]);
            acc[3][0] = fmaf(w.w, x0, acc[3][0]); acc[3][1] = fmaf(w.w, x1, acc[3][1]);
        }
        #pragma unroll
        for (int i = 0; i < 4; ++i) {
            int lrow = rowb + i;
            scratch[(split * 2 + 0) * 128 + lrow] = acc[i][0];
            scratch[(split * 2 + 1) * 128 + lrow] = acc[i][1];
        }
    }
    __syncthreads();
    if (tid < 256) {
        int m = tid >> 7, lr = tid & 127;
        float v = scratch[(0 * 2 + m) * 128 + lr];
        #pragma unroll
        for (int s = 1; s < 16; ++s) v += scratch[(s * 2 + m) * 128 + lr];
        v += bias[rank * JROWS_PER + lr];
        v = v > 0.f ? v : 0.f;
        uint32_t ad = s2u(&hid[m][rank * JROWS_PER + lr]);
        #pragma unroll
        for (int rk = 0; rk < CSIZE; ++rk) st_peer(ad, rk, v);
    }
    // caller cluster-syncs
}

__global__ __launch_bounds__(NTHREADS, 1) __cluster_dims__(CSIZE, 1, 1)
void rnnt_greedy_kernel(const float* __restrict__ x,
                        const int*   __restrict__ out_lens,
                        const float* __restrict__ emb,
                        const float* __restrict__ b0, const float* __restrict__ b1,
                        const float* __restrict__ bj1,
                        const float* __restrict__ Wj2, const float* __restrict__ bj2,
                        float* __restrict__ d_out, int write_lc)
{
    extern __shared__ __align__(16) char smem_raw[];
    Smem& S = *reinterpret_cast<Smem*>(smem_raw);

    const int tid  = threadIdx.x;
    const int lane = tid & 31;
    const int warp = tid >> 5;

    uint32_t rank;
    asm("mov.u32 %0, %%cluster_ctarank;" : "=r"(rank));
    const int cid   = blockIdx.x / CSIZE;
    const int bbase = cid * MB;

    __shared__ int s_last[MB], s_lc[MB], s_ti[MB], s_sa[MB], s_nb[MB], s_olen[MB];
    __shared__ int s_alldone;

    // ---- init ----
    for (int i = tid; i < MB * PRED; i += NTHREADS) {
        int m = i / PRED, j = i - m * PRED;
        S.L0in[m][PRED + j] = 0.f;   // h0 = 0
        S.L1in[m][PRED + j] = 0.f;   // h1 = 0
    }
    for (int i = tid; i < MB * UNITS_PER; i += NTHREADS) {
        int m = i / UNITS_PER, j = i - m * UNITS_PER;
        S.c0s[m][j] = 0.f; S.c1s[m][j] = 0.f;
    }
    for (int i = tid; i < MB * NSTEPS; i += NTHREADS) {
        int m = i / NSTEPS, j = i - m * NSTEPS;
        S.lt[m][j] = -1;
    }
    if (tid == 0) {
        #pragma unroll
        for (int m = 0; m < MB; ++m) {
            s_last[m] = -1; s_lc[m] = 0; s_ti[m] = 0; s_sa[m] = 0; s_nb[m] = 0;
            s_olen[m] = out_lens[bbase + m];
        }
        s_alldone = 0;
    }
    __syncthreads();
    CLUSTER_SYNC();

    for (int step = 0; step < NSTEPS; ++step) {
        const bool active = (s_alldone == 0);   // uniform across cluster

        // ---- P0: encoder frame -> zj[.][0:1024], embedding -> L0in[.][0:320] ----
        if (active) {
            for (int i = tid; i < MB * ENC; i += NTHREADS) {
                int m = i >> 10, col = i & (ENC - 1);
                int fi = s_ti[m]; if (fi > TLEN - 1) fi = TLEN - 1;
                S.zj[m][col] = x[((bbase + m) * TLEN + fi) * ENC + col];
            }
            for (int i = tid; i < MB * PRED; i += NTHREADS) {
                int m = i / PRED, col = i - m * PRED;
                int lab = s_last[m];
                int labc = lab > (VOCAB - 2) ? (VOCAB - 2) : lab;
                S.L0in[m][col] = (lab >= 0) ? emb[labc * PRED + col] : 0.0f;
            }
        }
        __syncthreads();

        // ---- P1: layer-0 gates (transposed GEMV; internal sync) ----
        if (active)
            gemv_gates_T(d_WiT0, d_WhT0, b0, S.L0in, S.g, S.scratch, (int)rank, tid);
        __syncthreads();

        // ---- P2: LSTM0 nonlinearity; broadcast h0p slice ----
        if (active && tid < MB * UNITS_PER) {
            int m = tid / UNITS_PER, lu = tid - m * UNITS_PER;
            float gi = S.g[m][lu],                 gf = S.g[m][UNITS_PER + lu];
            float gg = S.g[m][2 * UNITS_PER + lu], go = S.g[m][3 * UNITS_PER + lu];
            float c  = sigf(gf) * S.c0s[m][lu] + sigf(gi) * tanhf(gg);
            S.c0p[m][lu] = c;
            float h  = sigf(go) * tanhf(c);
            uint32_t a = s2u(&S.L1in[m][rank * UNITS_PER + lu]);
            #pragma unroll
            for (int rk = 0; rk < CSIZE; ++rk) st_peer(a, rk, h);
        }
        CLUSTER_SYNC();   // S1: full h0p in L1in[.][0:320] everywhere

        // ---- P3: layer-1 gates ----
        if (active)
            gemv_gates_T(d_WiT1, d_WhT1, b1, S.L1in, S.g, S.scratch, (int)rank, tid);
        __syncthreads();

        // ---- P4: LSTM1 nonlinearity; broadcast h1p slice ----
        if (active && tid < MB * UNITS_PER) {
            int m = tid / UNITS_PER, lu = tid - m * UNITS_PER;
            float gi = S.g[m][lu],                 gf = S.g[m][UNITS_PER + lu];
            float gg = S.g[m][2 * UNITS_PER + lu], go = S.g[m][3 * UNITS_PER + lu];
            float c  = sigf(gf) * S.c1s[m][lu] + sigf(gi) * tanhf(gg);
            S.c1p[m][lu] = c;
            float h  = sigf(go) * tanhf(c);
            uint32_t a = s2u(&S.zj[m][ENC + rank * UNITS_PER + lu]);
            #pragma unroll
            for (int rk = 0; rk < CSIZE; ++rk) st_peer(a, rk, h);
        }
        CLUSTER_SYNC();   // S2: full [f|h1p] in zj everywhere

        // ---- P5: joint hidden (transposed GEMV; internal sync; broadcasts hid) ----
        if (active)
            gemv_joint_T(d_Wj1T, bj1, S.zj, S.hid, S.scratch, (int)rank, tid);
        CLUSTER_SYNC();   // S3: full hid everywhere

        // ---- P6: logits (replicated; warp per vocab row) ----
        if (active) {
            for (int v = warp; v < VOCAB; v += (NTHREADS / 32)) {
                const float* w = Wj2 + v * JH + 16 * lane;
                float4 wv[4];
                #pragma unroll
                for (int j = 0; j < 4; ++j) wv[j] = *(const float4*)(w + 4 * j);
                float acc0 = 0.f, acc1 = 0.f;
                #pragma unroll
                for (int j = 0; j < 4; ++j) {
                    float4 h0v = *(const float4*)&S.hid[0][16 * lane + 4 * j];
                    float4 h1v = *(const float4*)&S.hid[1][16 * lane + 4 * j];
                    acc0 = fmaf(wv[j].x, h0v.x, acc0); acc0 = fmaf(wv[j].y, h0v.y, acc0);
                    acc0 = fmaf(wv[j].z, h0v.z, acc0); acc0 = fmaf(wv[j].w, h0v.w, acc0);
                    acc1 = fmaf(wv[j].x, h1v.x, acc1); acc1 = fmaf(wv[j].y, h1v.y, acc1);
                    acc1 = fmaf(wv[j].z, h1v.z, acc1); acc1 = fmaf(wv[j].w, h1v.w, acc1);
                }
                acc0 = wredsum(acc0);
                acc1 = wredsum(acc1);
                if (lane == 0) {
                    float bb = bj2[v];
                    S.logit[0][v] = acc0 + bb;
                    S.logit[1][v] = acc1 + bb;
                }
            }
        }
        __syncthreads();

        // ---- P7: argmax + control (replicated; identical in every CTA) ----
        if (active && tid == 0) {
            int ndone = 0;
            #pragma unroll
            for (int m = 0; m < MB; ++m) {
                float best = S.logit[m][0]; int k = 0;
                #pragma unroll
                for (int v = 1; v < VOCAB; ++v) {
                    float lv = S.logit[m][v];
                    if (lv > best) { best = lv; k = v; }
                }
                int ti = s_ti[m], sa = s_sa[m], lc = s_lc[m];
                bool blk = (k == BLANK);
                if (blk) ti += 1;
                bool done = (ti >= s_olen[m]);
                if (blk) sa = 0;
                bool nb = !(done || blk);
                if (nb) {
                    lc += 1;
                    if (lc <= NSTEPS - 1) S.lt[m][lc] += (k + 1);  // JAX scatter: OOB dropped
                    sa += 1;
                }
                {
                    int pos = lc; if (pos > NSTEPS - 1) pos = NSTEPS - 1;
                    s_last[m] = S.lt[m][pos];                       // JAX gather: clamp
                }
                if (sa >= MAXSYM) { ti += 1; sa = 0; }
                s_ti[m] = ti; s_sa[m] = sa; s_lc[m] = lc; s_nb[m] = nb ? 1 : 0;
                if (ti >= s_olen[m]) ndone += 1;
            }
            if (ndone == MB) s_alldone = 1;   // outputs frozen from here on
        }
        __syncthreads();

        // ---- P8: conditional state commit ----
        if (active) {
            for (int i = tid; i < MB * PRED; i += NTHREADS) {
                int m = i / PRED, u = i - m * PRED;
                if (s_nb[m]) {
                    S.L0in[m][PRED + u] = S.L1in[m][u];        // h0 <- h0p
                    S.L1in[m][PRED + u] = S.zj[m][ENC + u];    // h1 <- h1p
                }
            }
            if (tid < MB * UNITS_PER) {
                int m = tid / UNITS_PER, lu = tid - m * UNITS_PER;
                if (s_nb[m]) { S.c0s[m][lu] = S.c0p[m][lu]; S.c1s[m][lu] = S.c1p[m][lu]; }
            }
        }
        CLUSTER_SYNC();   // S4: protects h0p/h1p regions against next step's peer writes
    }

    // ---- output (rank 0): lt as float32, then lc ----
    if (rank == 0) {
        for (int m = 0; m < MB; ++m) {
            for (int i = tid; i < NSTEPS; i += NTHREADS)
                d_out[(bbase + m) * NSTEPS + i] = (float)S.lt[m][i];
        }
        if (tid == 0 && write_lc) {
            d_out[BATCH * NSTEPS + bbase + 0] = (float)s_lc[0];
            d_out[BATCH * NSTEPS + bbase + 1] = (float)s_lc[1];
        }
    }
}

extern "C" void kernel_launch(void* const* d_in, const int* in_sizes, int n_in,
                              void* d_out, int out_size) {
    const float* x        = (const float*)d_in[0];
    const int*   out_lens = (const int*)  d_in[1];
    const float* emb      = (const float*)d_in[2];
    const float* Wi0      = (const float*)d_in[3];
    const float* Wh0      = (const float*)d_in[4];
    const float* b0       = (const float*)d_in[5];
    const float* Wi1      = (const float*)d_in[6];
    const float* Wh1      = (const float*)d_in[7];
    const float* b1       = (const float*)d_in[8];
    const float* Wj1      = (const float*)d_in[9];
    const float* bj1      = (const float*)d_in[10];
    const float* Wj2      = (const float*)d_in[11];
    const float* bj2      = (const float*)d_in[12];

    int write_lc = (out_size >= BATCH * NSTEPS + BATCH) ? 1 : 0;

    // Opt-in to >48KB dynamic smem (idempotent; not a memory allocation).
    static int attr_done = 0;
    if (!attr_done) {
        cudaFuncSetAttribute(rnnt_greedy_kernel,
                             cudaFuncAttributeMaxDynamicSharedMemorySize, SMEM_BYTES);
        attr_done = 1;
    }

    dim3 tb(32, 8);
    transpose_kernel<<<512, tb>>>(Wi0, 4 * PRED, PRED, 0);
    transpose_kernel<<<512, tb>>>(Wh0, 4 * PRED, PRED, 1);
    transpose_kernel<<<512, tb>>>(Wi1, 4 * PRED, PRED, 2);
    transpose_kernel<<<512, tb>>>(Wh1, 4 * PRED, PRED, 3);
    transpose_kernel<<<512, tb>>>(Wj1, JH, ZDIM, 4);

    rnnt_greedy_kernel<<<(BATCH / MB) * CSIZE, NTHREADS, SMEM_BYTES>>>(
        x, out_lens, emb, b0, b1, bj1, Wj2, bj2,
        (float*)d_out, write_lc);
}